// round 12
// baseline (speedup 1.0000x reference)
#include <cuda_runtime.h>
#include <cuda_bf16.h>
#include <cstdint>
#include <math.h>

typedef unsigned int u32;

#define BB 32
#define TT 48
#define DD 768
#define HH 768
#define SS 128
#define VV 28996
#define H3 2304
#define VPAD 29056           // 227 * 128
#define KS 2304              // split-K: [hi | hi/lo | lo/hi]

// ---------------- scratch (static device globals; no allocation) -------------
__device__ float g_GI[TT * BB * H3];
__device__ float g_Hbuf[TT * BB * HH];
__device__ float g_h[BB * HH];
__device__ float g_ctx[BB * HH];
__device__ float g_E[BB * SS * HH];
__device__ float g_e0[BB * SS];
__device__ float g_sc[BB * SS];                // raw attention scores
__device__ __nv_bfloat16 g_As[TT * BB * KS];   // A' = [Ah | Ah | Al]
__device__ __nv_bfloat16 g_Bs[VPAD * KS];      // B' = [Bh | Bl | Bh]

// ---------------- PTX helpers (lvalue-safe wrappers) -------------------------
__device__ __forceinline__ void ldsm_x4(u32& r0, u32& r1, u32& r2, u32& r3,
                                        u32 addr) {
    asm volatile(
        "ldmatrix.sync.aligned.m8n8.x4.shared.b16 {%0,%1,%2,%3}, [%4];"
        : "=r"(r0), "=r"(r1), "=r"(r2), "=r"(r3)
        : "r"(addr));
}

__device__ __forceinline__ void mma_bf16_16816(float& c0, float& c1,
                                               float& c2, float& c3,
                                               u32 a0, u32 a1, u32 a2, u32 a3,
                                               u32 b0, u32 b1) {
    asm volatile(
        "mma.sync.aligned.m16n8k16.row.col.f32.bf16.bf16.f32 "
        "{%0,%1,%2,%3}, {%4,%5,%6,%7}, {%8,%9}, {%0,%1,%2,%3};"
        : "+f"(c0), "+f"(c1), "+f"(c2), "+f"(c3)
        : "r"(a0), "r"(a1), "r"(a2), "r"(a3), "r"(b0), "r"(b1));
}

__device__ __forceinline__ void cp_async16(u32 dst, const void* src) {
    asm volatile("cp.async.cg.shared.global [%0], [%1], 16;\n" ::"r"(dst),
                 "l"(src));
}

__device__ __forceinline__ void cp_commit() {
    asm volatile("cp.async.commit_group;\n");
}

template <int N>
__device__ __forceinline__ void cp_wait() {
    asm volatile("cp.async.wait_group %0;\n" ::"n"(N));
}

// ---------------- fused prologue ---------------------------------------------
// blocks [0,96): init_h | [96,960): GI gemm | [960,1728): E gemm | rest: e0
#define PROLOG_BLOCKS 1856
__global__ void __launch_bounds__(256)
k_prolog(const float* __restrict__ x, const float* __restrict__ Wih,
         const float* __restrict__ bih, const float* __restrict__ enc,
         const float* __restrict__ Watt, const float* __restrict__ batt,
         const float* __restrict__ hs) {
    __shared__ float as[16][68];
    __shared__ float bs[16][68];
    int bid = blockIdx.x;
    int tid = threadIdx.x;

    if (bid < 96) {
        int i = bid * 256 + tid;
        g_h[i] = hs[i];
        return;
    }
    if (bid < 960) {
        int id = bid - 96;
        int n0 = (id % 36) * 64, m0 = (id / 36) * 64;
        int tx = tid & 15, ty = tid >> 4;
        int lm = tid >> 2, lk = (tid & 3) * 4;

        int gm = m0 + lm;
        const float* aptr = x + ((gm & 31) * TT + (gm >> 5)) * DD;
        const float* bptr = Wih + (n0 + lm) * DD;

        float acc[4][4];
#pragma unroll
        for (int i = 0; i < 4; i++)
#pragma unroll
            for (int j = 0; j < 4; j++) acc[i][j] = 0.f;

        for (int k0 = 0; k0 < DD; k0 += 16) {
            float4 av = *(const float4*)(aptr + k0 + lk);
            float4 bv = *(const float4*)(bptr + k0 + lk);
            as[lk + 0][lm] = av.x; as[lk + 1][lm] = av.y;
            as[lk + 2][lm] = av.z; as[lk + 3][lm] = av.w;
            bs[lk + 0][lm] = bv.x; bs[lk + 1][lm] = bv.y;
            bs[lk + 2][lm] = bv.z; bs[lk + 3][lm] = bv.w;
            __syncthreads();
#pragma unroll
            for (int kk = 0; kk < 16; kk++) {
                float4 a4 = *(const float4*)&as[kk][ty * 4];
                float4 b4 = *(const float4*)&bs[kk][tx * 4];
                acc[0][0] += a4.x * b4.x; acc[0][1] += a4.x * b4.y;
                acc[0][2] += a4.x * b4.z; acc[0][3] += a4.x * b4.w;
                acc[1][0] += a4.y * b4.x; acc[1][1] += a4.y * b4.y;
                acc[1][2] += a4.y * b4.z; acc[1][3] += a4.y * b4.w;
                acc[2][0] += a4.z * b4.x; acc[2][1] += a4.z * b4.y;
                acc[2][2] += a4.z * b4.z; acc[2][3] += a4.z * b4.w;
                acc[3][0] += a4.w * b4.x; acc[3][1] += a4.w * b4.y;
                acc[3][2] += a4.w * b4.z; acc[3][3] += a4.w * b4.w;
            }
            __syncthreads();
        }
#pragma unroll
        for (int i = 0; i < 4; i++) {
            int m = m0 + ty * 4 + i;
#pragma unroll
            for (int j = 0; j < 4; j++) {
                int n = n0 + tx * 4 + j;
                g_GI[m * H3 + n] = acc[i][j] + bih[n];
            }
        }
        return;
    }
    if (bid < 1728) {
        int id = bid - 960;
        int n0 = (id % 12) * 64, m0 = (id / 12) * 64;
        int tx = tid & 15, ty = tid >> 4;
        int lm = tid >> 2, lk = (tid & 3) * 4;
        int lr = tid >> 4, lc = (tid & 15) * 4;

        const float* aptr = enc + (m0 + lm) * HH;

        float acc[4][4];
#pragma unroll
        for (int i = 0; i < 4; i++)
#pragma unroll
            for (int j = 0; j < 4; j++) acc[i][j] = 0.f;

        for (int k0 = 0; k0 < HH; k0 += 16) {
            float4 av = *(const float4*)(aptr + k0 + lk);
            float4 bv = *(const float4*)(Watt + (k0 + lr) * HH + n0 + lc);
            as[lk + 0][lm] = av.x; as[lk + 1][lm] = av.y;
            as[lk + 2][lm] = av.z; as[lk + 3][lm] = av.w;
            *(float4*)&bs[lr][lc] = bv;
            __syncthreads();
#pragma unroll
            for (int kk = 0; kk < 16; kk++) {
                float4 a4 = *(const float4*)&as[kk][ty * 4];
                float4 b4 = *(const float4*)&bs[kk][tx * 4];
                acc[0][0] += a4.x * b4.x; acc[0][1] += a4.x * b4.y;
                acc[0][2] += a4.x * b4.z; acc[0][3] += a4.x * b4.w;
                acc[1][0] += a4.y * b4.x; acc[1][1] += a4.y * b4.y;
                acc[1][2] += a4.y * b4.z; acc[1][3] += a4.y * b4.w;
                acc[2][0] += a4.z * b4.x; acc[2][1] += a4.z * b4.y;
                acc[2][2] += a4.z * b4.z; acc[2][3] += a4.z * b4.w;
                acc[3][0] += a4.w * b4.x; acc[3][1] += a4.w * b4.y;
                acc[3][2] += a4.w * b4.z; acc[3][3] += a4.w * b4.w;
            }
            __syncthreads();
        }
#pragma unroll
        for (int i = 0; i < 4; i++) {
            int m = m0 + ty * 4 + i;
#pragma unroll
            for (int j = 0; j < 4; j++) {
                g_E[m * HH + n0 + tx * 4 + j] = acc[i][j];
            }
        }
        return;
    }
    {
        int id = bid - 1728;
        int gw = id * 8 + (tid >> 5);
        int lane = tid & 31;
        for (int r = gw; r < BB * SS; r += 1024) {
            const float4* e4 = (const float4*)(enc + r * HH);
            const float4* b4 = (const float4*)batt;
            float s = 0.f;
#pragma unroll
            for (int c = 0; c < 6; c++) {
                float4 ev = e4[c * 32 + lane];
                float4 bv = b4[c * 32 + lane];
                s += ev.x * bv.x + ev.y * bv.y + ev.z * bv.z + ev.w * bv.w;
            }
#pragma unroll
            for (int o = 16; o > 0; o >>= 1)
                s += __shfl_down_sync(0xffffffffu, s, o);
            if (lane == 0) g_e0[r] = s;
        }
    }
}

// ---------------- GRU step (fused gh GEMM + gates) ---------------------------
#define GRU_SMEM ((768 * 32 + 18 * 768 + 3 * 24 * 32) * 4)
__global__ void k_gru2(const float* __restrict__ Whh,
                       const float* __restrict__ bhh, int t) {
    extern __shared__ float sm[];
    float* h_s = sm;
    float* w_s = sm + 768 * 32;
    float* red = w_s + 18 * 768;
    int tid = threadIdx.x;
    int j0 = blockIdx.x * 6;

    for (int i = tid; i < 6144; i += 768) {
        int b = i & 31, kq = i >> 5;
        float4 v = *(const float4*)(g_h + b * HH + kq * 4);
        h_s[(kq * 4 + 0) * 32 + b] = v.x;
        h_s[(kq * 4 + 1) * 32 + b] = v.y;
        h_s[(kq * 4 + 2) * 32 + b] = v.z;
        h_s[(kq * 4 + 3) * 32 + b] = v.w;
    }
    for (int i = tid; i < 3456; i += 768) {
        int row = i / 192, c4 = i % 192;
        int g = row / 6, jl = row % 6;
        *(float4*)(w_s + row * 768 + c4 * 4) =
            *(const float4*)(Whh + (g * HH + j0 + jl) * HH + c4 * 4);
    }
    __syncthreads();

    int b = tid & 31, q = tid >> 5;
    int jl = q % 6, qt = q / 6;
    int kbeg = qt * 192;
    const float4* w0 = (const float4*)(w_s + (0 + jl) * 768 + kbeg);
    const float4* w1 = (const float4*)(w_s + (6 + jl) * 768 + kbeg);
    const float4* w2 = (const float4*)(w_s + (12 + jl) * 768 + kbeg);
    const float* hp = h_s + kbeg * 32 + b;
    float a0 = 0.f, a1 = 0.f, a2 = 0.f;
#pragma unroll 8
    for (int c = 0; c < 48; c++) {
        float4 v0 = w0[c], v1 = w1[c], v2 = w2[c];
        float h0 = hp[c * 128 + 0], h1 = hp[c * 128 + 32];
        float h2 = hp[c * 128 + 64], h3 = hp[c * 128 + 96];
        a0 += h0 * v0.x + h1 * v0.y + h2 * v0.z + h3 * v0.w;
        a1 += h0 * v1.x + h1 * v1.y + h2 * v1.z + h3 * v1.w;
        a2 += h0 * v2.x + h1 * v2.y + h2 * v2.z + h3 * v2.w;
    }
    red[(0 * 24 + q) * 32 + b] = a0;
    red[(1 * 24 + q) * 32 + b] = a1;
    red[(2 * 24 + q) * 32 + b] = a2;
    __syncthreads();

    if (tid < 192) {
        int b2 = tid & 31, j2 = tid >> 5, j = j0 + j2;
        float ar = 0.f, az = 0.f, an = 0.f;
#pragma unroll
        for (int qq = 0; qq < 4; qq++) {
            int q2 = qq * 6 + j2;
            ar += red[(0 * 24 + q2) * 32 + b2];
            az += red[(1 * 24 + q2) * 32 + b2];
            an += red[(2 * 24 + q2) * 32 + b2];
        }
        const float* gi = g_GI + (t * BB + b2) * H3;
        float r = 1.f / (1.f + expf(-(gi[j] + ar + bhh[j])));
        float z = 1.f / (1.f + expf(-(gi[HH + j] + az + bhh[HH + j])));
        float n = tanhf(gi[2 * HH + j] + r * (an + bhh[2 * HH + j]));
        float hprev = g_h[b2 * HH + j];
        g_Hbuf[(t * BB + b2) * HH + j] = (1.f - z) * n + z * hprev;
    }
}

// ---------------- scores: g_sc[b][s] = h . E[b,s] + e0  (256 blocks) ---------
// grid 256 = 32 b x 8 s-chunks of 16; 8 warps/block, each warp 2 s-rows.
__global__ void __launch_bounds__(256)
k_score(int t) {
    __shared__ __align__(16) float hg[768];
    int b = blockIdx.x >> 3, sc = blockIdx.x & 7;
    int tid = threadIdx.x;

    for (int i = tid; i < 768; i += 256) hg[i] = g_Hbuf[(t * BB + b) * HH + i];
    __syncthreads();

    int w = tid >> 5, lane = tid & 31;
    const float4* hg4 = (const float4*)hg;
#pragma unroll
    for (int i = 0; i < 2; i++) {
        int s = sc * 16 + w * 2 + i;
        const float4* e4 = (const float4*)(g_E + (b * SS + s) * HH);
        float d = 0.f;
#pragma unroll
        for (int c = 0; c < 6; c++) {
            float4 ev = e4[c * 32 + lane];
            float4 hv = hg4[c * 32 + lane];
            d += ev.x * hv.x + ev.y * hv.y + ev.z * hv.z + ev.w * hv.w;
        }
#pragma unroll
        for (int o = 16; o > 0; o >>= 1) d += __shfl_down_sync(0xffffffffu, d, o);
        if (lane == 0) g_sc[b * SS + s] = d + g_e0[b * SS + s];
    }
}

// ---------------- ctx: softmax (recomputed per block) + weighted sum ---------
// grid 192 = 32 b x 6 dim-chunks of 128; 128 threads.
__global__ void __launch_bounds__(128)
k_ctx(const float* __restrict__ enc, int t) {
    __shared__ float p[128];
    __shared__ float red[128];
    int b = blockIdx.x / 6, hc = blockIdx.x % 6;
    int tid = threadIdx.x;

    {
        float v = g_sc[b * SS + tid];
        p[tid] = v;
        red[tid] = v;
    }
    __syncthreads();
    for (int o = 64; o > 0; o >>= 1) {
        if (tid < o) red[tid] = fmaxf(red[tid], red[tid + o]);
        __syncthreads();
    }
    float mx = red[0];
    __syncthreads();
    {
        float e = expf(p[tid] - mx);
        p[tid] = e;
        red[tid] = e;
    }
    __syncthreads();
    for (int o = 64; o > 0; o >>= 1) {
        if (tid < o) red[tid] += red[tid + o];
        __syncthreads();
    }
    float inv = 1.f / red[0];
    __syncthreads();
    p[tid] *= inv;
    __syncthreads();

    int dim = hc * 128 + tid;
    float acc = 0.f;
    const float* ep = enc + (b * SS) * HH + dim;
#pragma unroll 16
    for (int s = 0; s < SS; s++) acc += p[s] * ep[s * HH];
    g_ctx[b * HH + dim] = acc;
}

// ---------------- carry update ----------------------------------------------
#define ATTH_SMEM ((768 * 32 + 6 * 1536 + 24 * 32) * 4)
__global__ void k_atth2(const float* __restrict__ Wctx,
                        const float* __restrict__ bctx, int t) {
    extern __shared__ float sm[];
    float* in_s = sm;
    float* w_s = sm + 768 * 32;
    float* red = w_s + 6 * 1536;
    int tid = threadIdx.x;
    int j0 = blockIdx.x * 6;

    for (int i = tid; i < 2304; i += 768) {
        int row = i / 384, c4 = i % 384;
        *(float4*)(w_s + row * 1536 + c4 * 4) =
            *(const float4*)(Wctx + (j0 + row) * (2 * HH) + c4 * 4);
    }

    int b = tid & 31, q = tid >> 5;
    int jl = q % 6, sub = q / 6;
    float acc = 0.f;
#pragma unroll
    for (int ph = 0; ph < 2; ph++) {
        const float* src = ph ? (g_Hbuf + (t * BB) * HH) : g_ctx;
        __syncthreads();
        for (int i = tid; i < 6144; i += 768) {
            int bb = i & 31, kq = i >> 5;
            float4 v = *(const float4*)(src + bb * HH + kq * 4);
            in_s[(kq * 4 + 0) * 32 + bb] = v.x;
            in_s[(kq * 4 + 1) * 32 + bb] = v.y;
            in_s[(kq * 4 + 2) * 32 + bb] = v.z;
            in_s[(kq * 4 + 3) * 32 + bb] = v.w;
        }
        __syncthreads();
        const float4* wp = (const float4*)(w_s + jl * 1536 + ph * 768 + sub * 192);
        const float* ip = in_s + sub * 192 * 32 + b;
#pragma unroll 8
        for (int c = 0; c < 48; c++) {
            float4 v = wp[c];
            float h0 = ip[c * 128 + 0], h1 = ip[c * 128 + 32];
            float h2 = ip[c * 128 + 64], h3 = ip[c * 128 + 96];
            acc += h0 * v.x + h1 * v.y + h2 * v.z + h3 * v.w;
        }
    }
    red[q * 32 + b] = acc;
    __syncthreads();
    if (tid < 192) {
        int b2 = tid & 31, j2 = tid >> 5, j = j0 + j2;
        float s = 0.f;
#pragma unroll
        for (int qq = 0; qq < 4; qq++) s += red[(qq * 6 + j2) * 32 + b2];
        g_h[b2 * HH + j] = tanhf(s + bctx[j]);
    }
}

// ---------------- bf16 split conversions ------------------------------------
__device__ __forceinline__ void split4(float4 v, __nv_bfloat16* hi,
                                       __nv_bfloat16* lo) {
    float f[4];
    f[0] = v.x; f[1] = v.y; f[2] = v.z; f[3] = v.w;
#pragma unroll
    for (int i = 0; i < 4; i++) {
        __nv_bfloat16 h = __float2bfloat16_rn(f[i]);
        hi[i] = h;
        lo[i] = __float2bfloat16_rn(f[i] - __bfloat162float(h));
    }
}

// B' = [Bh | Bl | Bh], rows padded to VPAD with zeros
__global__ void k_cvtB(const float* __restrict__ Wp) {
    long idx = (long)blockIdx.x * blockDim.x + threadIdx.x;
    if (idx >= (long)VPAD * 192) return;
    int row = (int)(idx / 192), c4 = (int)(idx % 192);
    float4 v = (row < VV) ? *(const float4*)(Wp + (long)row * HH + c4 * 4)
                          : make_float4(0.f, 0.f, 0.f, 0.f);
    __nv_bfloat16 hi[4], lo[4];
    split4(v, hi, lo);
    __nv_bfloat16* dst = g_Bs + (long)row * KS + c4 * 4;
    *(uint2*)(dst) = *(uint2*)hi;
    *(uint2*)(dst + HH) = *(uint2*)lo;
    *(uint2*)(dst + 2 * HH) = *(uint2*)hi;
}

// A' = [Ah | Ah | Al]
__global__ void k_cvtA() {
    int idx = blockIdx.x * blockDim.x + threadIdx.x;
    if (idx >= TT * BB * 192) return;
    int row = idx / 192, c4 = idx % 192;
    float4 v = *(const float4*)(g_Hbuf + row * HH + c4 * 4);
    __nv_bfloat16 hi[4], lo[4];
    split4(v, hi, lo);
    __nv_bfloat16* dst = g_As + row * KS + c4 * 4;
    *(uint2*)(dst) = *(uint2*)hi;
    *(uint2*)(dst + HH) = *(uint2*)hi;
    *(uint2*)(dst + 2 * HH) = *(uint2*)lo;
}

// ---------------- logits GEMM on tensor cores (mma.sync bf16) ----------------
#define LDP 40  // padded smem row length in bf16 (80 bytes)
__global__ void __launch_bounds__(256)
k_predmma(const float* __restrict__ bp, float* __restrict__ out) {
    __shared__ __nv_bfloat16 sA[2][128 * LDP];
    __shared__ __nv_bfloat16 sB[2][128 * LDP];

    int tid = threadIdx.x;
    int lane = tid & 31, wid = tid >> 5;
    int m0 = blockIdx.x * 128, n0 = blockIdx.y * 128;
    int warp_m = (wid >> 1) * 32;
    int warp_n = (wid & 1) * 64;

    const __nv_bfloat16* gA = g_As + (long)m0 * KS;
    const __nv_bfloat16* gB = g_Bs + (long)n0 * KS;

    float acc[2][8][4];
#pragma unroll
    for (int i = 0; i < 2; i++)
#pragma unroll
        for (int j = 0; j < 8; j++)
#pragma unroll
            for (int r = 0; r < 4; r++) acc[i][j][r] = 0.f;

    int ar0 = tid >> 2, ac0 = (tid & 3) * 8;
    int ar1 = (tid + 256) >> 2, ac1 = ((tid + 256) & 3) * 8;

    u32 sA0 = (u32)__cvta_generic_to_shared(&sA[0][0]);
    u32 sB0 = (u32)__cvta_generic_to_shared(&sB[0][0]);
    const u32 stageA = 128 * LDP * 2;
    const u32 stageB = 128 * LDP * 2;

    cp_async16(sA0 + (ar0 * LDP + ac0) * 2, gA + (long)ar0 * KS + ac0);
    cp_async16(sA0 + (ar1 * LDP + ac1) * 2, gA + (long)ar1 * KS + ac1);
    cp_async16(sB0 + (ar0 * LDP + ac0) * 2, gB + (long)ar0 * KS + ac0);
    cp_async16(sB0 + (ar1 * LDP + ac1) * 2, gB + (long)ar1 * KS + ac1);
    cp_commit();

    const int NIT = KS / 32;  // 72
    for (int it = 0; it < NIT; it++) {
        int buf = it & 1;
        if (it + 1 < NIT) {
            int k0 = (it + 1) * 32;
            u32 dA = sA0 + (buf ^ 1) * stageA;
            u32 dB = sB0 + (buf ^ 1) * stageB;
            cp_async16(dA + (ar0 * LDP + ac0) * 2, gA + (long)ar0 * KS + k0 + ac0);
            cp_async16(dA + (ar1 * LDP + ac1) * 2, gA + (long)ar1 * KS + k0 + ac1);
            cp_async16(dB + (ar0 * LDP + ac0) * 2, gB + (long)ar0 * KS + k0 + ac0);
            cp_async16(dB + (ar1 * LDP + ac1) * 2, gB + (long)ar1 * KS + k0 + ac1);
            cp_commit();
            cp_wait<1>();
        } else {
            cp_wait<0>();
        }
        __syncthreads();

        u32 baseA = sA0 + buf * stageA;
        u32 baseB = sB0 + buf * stageB;
#pragma unroll
        for (int ks = 0; ks < 2; ks++) {
            u32 areg[2][4];
#pragma unroll
            for (int mi = 0; mi < 2; mi++) {
                u32 addr = baseA +
                    ((warp_m + mi * 16 + (lane & 15)) * LDP +
                     ks * 16 + (lane >> 4) * 8) * 2;
                ldsm_x4(areg[mi][0], areg[mi][1], areg[mi][2], areg[mi][3],
                        addr);
            }
            u32 breg[4][4];
#pragma unroll
            for (int np = 0; np < 4; np++) {
                u32 addr = baseB +
                    ((warp_n + np * 16 + (lane & 15)) * LDP +
                     ks * 16 + (lane >> 4) * 8) * 2;
                ldsm_x4(breg[np][0], breg[np][1], breg[np][2], breg[np][3],
                        addr);
            }
#pragma unroll
            for (int mi = 0; mi < 2; mi++) {
#pragma unroll
                for (int nf = 0; nf < 8; nf++) {
                    int np = nf >> 1;
                    u32 b0 = (nf & 1) ? breg[np][1] : breg[np][0];
                    u32 b1 = (nf & 1) ? breg[np][3] : breg[np][2];
                    mma_bf16_16816(acc[mi][nf][0], acc[mi][nf][1],
                                   acc[mi][nf][2], acc[mi][nf][3],
                                   areg[mi][0], areg[mi][1], areg[mi][2],
                                   areg[mi][3], b0, b1);
                }
            }
        }
        __syncthreads();
    }

#pragma unroll
    for (int mi = 0; mi < 2; mi++) {
        int mA = m0 + warp_m + mi * 16 + (lane >> 2);
#pragma unroll
        for (int half = 0; half < 2; half++) {
            int m = mA + half * 8;
            int t = m >> 5, bb = m & 31;
            float* orow = out + (long)(bb * TT + t) * VV;
#pragma unroll
            for (int nf = 0; nf < 8; nf++) {
                int n = n0 + warp_n + nf * 8 + (lane & 3) * 2;
                if (n < VV) {
                    float2 bias = *(const float2*)(bp + n);
                    float2 v;
                    v.x = acc[mi][nf][half * 2 + 0] + bias.x;
                    v.y = acc[mi][nf][half * 2 + 1] + bias.y;
                    *(float2*)(orow + n) = v;
                }
            }
        }
    }
}

// ---------------- launcher ---------------------------------------------------
extern "C" void kernel_launch(void* const* d_in, const int* in_sizes, int n_in,
                              void* d_out, int out_size) {
    const float* x    = (const float*)d_in[0];
    const float* h0   = (const float*)d_in[1];
    const float* enc  = (const float*)d_in[2];
    const float* Wih  = (const float*)d_in[3];
    const float* Whh  = (const float*)d_in[4];
    const float* bih  = (const float*)d_in[5];
    const float* bhh  = (const float*)d_in[6];
    const float* Wp   = (const float*)d_in[7];
    const float* bp   = (const float*)d_in[8];
    const float* Watt = (const float*)d_in[9];
    const float* batt = (const float*)d_in[10];
    const float* Wctx = (const float*)d_in[11];
    const float* bctx = (const float*)d_in[12];
    float* out = (float*)d_out;

    cudaFuncSetAttribute(k_gru2, cudaFuncAttributeMaxDynamicSharedMemorySize,
                         GRU_SMEM);
    cudaFuncSetAttribute(k_atth2, cudaFuncAttributeMaxDynamicSharedMemorySize,
                         ATTH_SMEM);

    k_prolog<<<PROLOG_BLOCKS, 256>>>(x, Wih, bih, enc, Watt, batt, h0);
    k_cvtB<<<(VPAD * 192 + 255) / 256, 256>>>(Wp);

    for (int t = 0; t < TT; t++) {
        k_gru2<<<128, 768, GRU_SMEM>>>(Whh, bhh, t);
        k_score<<<BB * 8, 256>>>(t);
        k_ctx<<<BB * 6, 128>>>(enc, t);
        k_atth2<<<128, 768, ATTH_SMEM>>>(Wctx, bctx, t);
    }

    k_cvtA<<<(TT * BB * 192 + 255) / 256, 256>>>();
    k_predmma<<<dim3((TT * BB) / 128, VPAD / 128), 256>>>(bp, out);
}

// round 13
// speedup vs baseline: 1.4894x; 1.4894x over previous
#include <cuda_runtime.h>
#include <cuda_bf16.h>
#include <cstdint>
#include <math.h>

typedef unsigned int u32;

#define BB 32
#define TT 48
#define DD 768
#define HH 768
#define SS 128
#define VV 28996
#define H3 2304
#define VPAD 29056           // 227 * 128
#define KS 2304              // split-K: [hi | hi/lo | lo/hi]

// ---------------- scratch (static device globals; no allocation) -------------
__device__ float g_GI[TT * BB * H3];
__device__ float g_Hbuf[TT * BB * HH];
__device__ float g_h[BB * HH];
__device__ float g_ctx[BB * HH];
__device__ float g_E[BB * SS * HH];
__device__ float g_e0[BB * SS];
__device__ float g_sc[BB * SS];                // raw attention scores
__device__ __nv_bfloat16 g_As[TT * BB * KS];   // A' = [Ah | Ah | Al]
__device__ __nv_bfloat16 g_Bs[VPAD * KS];      // B' = [Bh | Bl | Bh]

// ---------------- PTX helpers (lvalue-safe wrappers) -------------------------
__device__ __forceinline__ void ldsm_x4(u32& r0, u32& r1, u32& r2, u32& r3,
                                        u32 addr) {
    asm volatile(
        "ldmatrix.sync.aligned.m8n8.x4.shared.b16 {%0,%1,%2,%3}, [%4];"
        : "=r"(r0), "=r"(r1), "=r"(r2), "=r"(r3)
        : "r"(addr));
}

__device__ __forceinline__ void mma_bf16_16816(float& c0, float& c1,
                                               float& c2, float& c3,
                                               u32 a0, u32 a1, u32 a2, u32 a3,
                                               u32 b0, u32 b1) {
    asm volatile(
        "mma.sync.aligned.m16n8k16.row.col.f32.bf16.bf16.f32 "
        "{%0,%1,%2,%3}, {%4,%5,%6,%7}, {%8,%9}, {%0,%1,%2,%3};"
        : "+f"(c0), "+f"(c1), "+f"(c2), "+f"(c3)
        : "r"(a0), "r"(a1), "r"(a2), "r"(a3), "r"(b0), "r"(b1));
}

__device__ __forceinline__ void cp_async16(u32 dst, const void* src) {
    asm volatile("cp.async.cg.shared.global [%0], [%1], 16;\n" ::"r"(dst),
                 "l"(src));
}

__device__ __forceinline__ void cp_commit() {
    asm volatile("cp.async.commit_group;\n");
}

template <int N>
__device__ __forceinline__ void cp_wait() {
    asm volatile("cp.async.wait_group %0;\n" ::"n"(N));
}

// ---------------- fused prologue ---------------------------------------------
// blocks [0,96): init_h | [96,960): GI gemm | [960,1728): E gemm | rest: e0
#define PROLOG_BLOCKS 1856
__global__ void __launch_bounds__(256)
k_prolog(const float* __restrict__ x, const float* __restrict__ Wih,
         const float* __restrict__ bih, const float* __restrict__ enc,
         const float* __restrict__ Watt, const float* __restrict__ batt,
         const float* __restrict__ hs) {
    __shared__ float as[16][68];
    __shared__ float bs[16][68];
    int bid = blockIdx.x;
    int tid = threadIdx.x;

    if (bid < 96) {
        int i = bid * 256 + tid;
        g_h[i] = hs[i];
        return;
    }
    if (bid < 960) {
        int id = bid - 96;
        int n0 = (id % 36) * 64, m0 = (id / 36) * 64;
        int tx = tid & 15, ty = tid >> 4;
        int lm = tid >> 2, lk = (tid & 3) * 4;

        int gm = m0 + lm;
        const float* aptr = x + ((gm & 31) * TT + (gm >> 5)) * DD;
        const float* bptr = Wih + (n0 + lm) * DD;

        float acc[4][4];
#pragma unroll
        for (int i = 0; i < 4; i++)
#pragma unroll
            for (int j = 0; j < 4; j++) acc[i][j] = 0.f;

        for (int k0 = 0; k0 < DD; k0 += 16) {
            float4 av = *(const float4*)(aptr + k0 + lk);
            float4 bv = *(const float4*)(bptr + k0 + lk);
            as[lk + 0][lm] = av.x; as[lk + 1][lm] = av.y;
            as[lk + 2][lm] = av.z; as[lk + 3][lm] = av.w;
            bs[lk + 0][lm] = bv.x; bs[lk + 1][lm] = bv.y;
            bs[lk + 2][lm] = bv.z; bs[lk + 3][lm] = bv.w;
            __syncthreads();
#pragma unroll
            for (int kk = 0; kk < 16; kk++) {
                float4 a4 = *(const float4*)&as[kk][ty * 4];
                float4 b4 = *(const float4*)&bs[kk][tx * 4];
                acc[0][0] += a4.x * b4.x; acc[0][1] += a4.x * b4.y;
                acc[0][2] += a4.x * b4.z; acc[0][3] += a4.x * b4.w;
                acc[1][0] += a4.y * b4.x; acc[1][1] += a4.y * b4.y;
                acc[1][2] += a4.y * b4.z; acc[1][3] += a4.y * b4.w;
                acc[2][0] += a4.z * b4.x; acc[2][1] += a4.z * b4.y;
                acc[2][2] += a4.z * b4.z; acc[2][3] += a4.z * b4.w;
                acc[3][0] += a4.w * b4.x; acc[3][1] += a4.w * b4.y;
                acc[3][2] += a4.w * b4.z; acc[3][3] += a4.w * b4.w;
            }
            __syncthreads();
        }
#pragma unroll
        for (int i = 0; i < 4; i++) {
            int m = m0 + ty * 4 + i;
#pragma unroll
            for (int j = 0; j < 4; j++) {
                int n = n0 + tx * 4 + j;
                g_GI[m * H3 + n] = acc[i][j] + bih[n];
            }
        }
        return;
    }
    if (bid < 1728) {
        int id = bid - 960;
        int n0 = (id % 12) * 64, m0 = (id / 12) * 64;
        int tx = tid & 15, ty = tid >> 4;
        int lm = tid >> 2, lk = (tid & 3) * 4;
        int lr = tid >> 4, lc = (tid & 15) * 4;

        const float* aptr = enc + (m0 + lm) * HH;

        float acc[4][4];
#pragma unroll
        for (int i = 0; i < 4; i++)
#pragma unroll
            for (int j = 0; j < 4; j++) acc[i][j] = 0.f;

        for (int k0 = 0; k0 < HH; k0 += 16) {
            float4 av = *(const float4*)(aptr + k0 + lk);
            float4 bv = *(const float4*)(Watt + (k0 + lr) * HH + n0 + lc);
            as[lk + 0][lm] = av.x; as[lk + 1][lm] = av.y;
            as[lk + 2][lm] = av.z; as[lk + 3][lm] = av.w;
            *(float4*)&bs[lr][lc] = bv;
            __syncthreads();
#pragma unroll
            for (int kk = 0; kk < 16; kk++) {
                float4 a4 = *(const float4*)&as[kk][ty * 4];
                float4 b4 = *(const float4*)&bs[kk][tx * 4];
                acc[0][0] += a4.x * b4.x; acc[0][1] += a4.x * b4.y;
                acc[0][2] += a4.x * b4.z; acc[0][3] += a4.x * b4.w;
                acc[1][0] += a4.y * b4.x; acc[1][1] += a4.y * b4.y;
                acc[1][2] += a4.y * b4.z; acc[1][3] += a4.y * b4.w;
                acc[2][0] += a4.z * b4.x; acc[2][1] += a4.z * b4.y;
                acc[2][2] += a4.z * b4.z; acc[2][3] += a4.z * b4.w;
                acc[3][0] += a4.w * b4.x; acc[3][1] += a4.w * b4.y;
                acc[3][2] += a4.w * b4.z; acc[3][3] += a4.w * b4.w;
            }
            __syncthreads();
        }
#pragma unroll
        for (int i = 0; i < 4; i++) {
            int m = m0 + ty * 4 + i;
#pragma unroll
            for (int j = 0; j < 4; j++) {
                g_E[m * HH + n0 + tx * 4 + j] = acc[i][j];
            }
        }
        return;
    }
    {
        int id = bid - 1728;
        int gw = id * 8 + (tid >> 5);
        int lane = tid & 31;
        for (int r = gw; r < BB * SS; r += 1024) {
            const float4* e4 = (const float4*)(enc + r * HH);
            const float4* b4 = (const float4*)batt;
            float s = 0.f;
#pragma unroll
            for (int c = 0; c < 6; c++) {
                float4 ev = e4[c * 32 + lane];
                float4 bv = b4[c * 32 + lane];
                s += ev.x * bv.x + ev.y * bv.y + ev.z * bv.z + ev.w * bv.w;
            }
#pragma unroll
            for (int o = 16; o > 0; o >>= 1)
                s += __shfl_down_sync(0xffffffffu, s, o);
            if (lane == 0) g_e0[r] = s;
        }
    }
}

// ---------------- GRU step (fused gh GEMM + gates) ---------------------------
#define GRU_SMEM ((768 * 32 + 18 * 768 + 3 * 24 * 32) * 4)
__global__ void k_gru2(const float* __restrict__ Whh,
                       const float* __restrict__ bhh, int t) {
    extern __shared__ float sm[];
    float* h_s = sm;
    float* w_s = sm + 768 * 32;
    float* red = w_s + 18 * 768;
    int tid = threadIdx.x;
    int j0 = blockIdx.x * 6;

    for (int i = tid; i < 6144; i += 768) {
        int b = i & 31, kq = i >> 5;
        float4 v = *(const float4*)(g_h + b * HH + kq * 4);
        h_s[(kq * 4 + 0) * 32 + b] = v.x;
        h_s[(kq * 4 + 1) * 32 + b] = v.y;
        h_s[(kq * 4 + 2) * 32 + b] = v.z;
        h_s[(kq * 4 + 3) * 32 + b] = v.w;
    }
    for (int i = tid; i < 3456; i += 768) {
        int row = i / 192, c4 = i % 192;
        int g = row / 6, jl = row % 6;
        *(float4*)(w_s + row * 768 + c4 * 4) =
            *(const float4*)(Whh + (g * HH + j0 + jl) * HH + c4 * 4);
    }
    __syncthreads();

    int b = tid & 31, q = tid >> 5;
    int jl = q % 6, qt = q / 6;
    int kbeg = qt * 192;
    const float4* w0 = (const float4*)(w_s + (0 + jl) * 768 + kbeg);
    const float4* w1 = (const float4*)(w_s + (6 + jl) * 768 + kbeg);
    const float4* w2 = (const float4*)(w_s + (12 + jl) * 768 + kbeg);
    const float* hp = h_s + kbeg * 32 + b;
    float a0 = 0.f, a1 = 0.f, a2 = 0.f;
#pragma unroll 8
    for (int c = 0; c < 48; c++) {
        float4 v0 = w0[c], v1 = w1[c], v2 = w2[c];
        float h0 = hp[c * 128 + 0], h1 = hp[c * 128 + 32];
        float h2 = hp[c * 128 + 64], h3 = hp[c * 128 + 96];
        a0 += h0 * v0.x + h1 * v0.y + h2 * v0.z + h3 * v0.w;
        a1 += h0 * v1.x + h1 * v1.y + h2 * v1.z + h3 * v1.w;
        a2 += h0 * v2.x + h1 * v2.y + h2 * v2.z + h3 * v2.w;
    }
    red[(0 * 24 + q) * 32 + b] = a0;
    red[(1 * 24 + q) * 32 + b] = a1;
    red[(2 * 24 + q) * 32 + b] = a2;
    __syncthreads();

    if (tid < 192) {
        int b2 = tid & 31, j2 = tid >> 5, j = j0 + j2;
        float ar = 0.f, az = 0.f, an = 0.f;
#pragma unroll
        for (int qq = 0; qq < 4; qq++) {
            int q2 = qq * 6 + j2;
            ar += red[(0 * 24 + q2) * 32 + b2];
            az += red[(1 * 24 + q2) * 32 + b2];
            an += red[(2 * 24 + q2) * 32 + b2];
        }
        const float* gi = g_GI + (t * BB + b2) * H3;
        float r = 1.f / (1.f + expf(-(gi[j] + ar + bhh[j])));
        float z = 1.f / (1.f + expf(-(gi[HH + j] + az + bhh[HH + j])));
        float n = tanhf(gi[2 * HH + j] + r * (an + bhh[2 * HH + j]));
        float hprev = g_h[b2 * HH + j];
        g_Hbuf[(t * BB + b2) * HH + j] = (1.f - z) * n + z * hprev;
    }
}

// ---------------- scores: g_sc[b][s] = h . E[b,s] + e0  (256 blocks) ---------
// grid 256 = 32 b x 8 s-chunks of 16; 8 warps/block, each warp 2 s-rows.
// (measured 9.4us vs 10.2us for the 128-block variant)
__global__ void __launch_bounds__(256)
k_score(int t) {
    __shared__ __align__(16) float hg[768];
    int b = blockIdx.x >> 3, sc = blockIdx.x & 7;
    int tid = threadIdx.x;

    for (int i = tid; i < 768; i += 256) hg[i] = g_Hbuf[(t * BB + b) * HH + i];
    __syncthreads();

    int w = tid >> 5, lane = tid & 31;
    const float4* hg4 = (const float4*)hg;
#pragma unroll
    for (int i = 0; i < 2; i++) {
        int s = sc * 16 + w * 2 + i;
        const float4* e4 = (const float4*)(g_E + (b * SS + s) * HH);
        float d = 0.f;
#pragma unroll
        for (int c = 0; c < 6; c++) {
            float4 ev = e4[c * 32 + lane];
            float4 hv = hg4[c * 32 + lane];
            d += ev.x * hv.x + ev.y * hv.y + ev.z * hv.z + ev.w * hv.w;
        }
#pragma unroll
        for (int o = 16; o > 0; o >>= 1) d += __shfl_down_sync(0xffffffffu, d, o);
        if (lane == 0) g_sc[b * SS + s] = d + g_e0[b * SS + s];
    }
}

// ---------------- ctx: softmax (recomputed per block) + weighted sum ---------
// grid 128 = 32 b x 4 dim-chunks of 192; 192 threads, unroll 8 (R11 config —
// the 128-thread/unroll-16 variant overflowed the L1tex queue and regressed).
__global__ void __launch_bounds__(192)
k_ctx(const float* __restrict__ enc, int t) {
    __shared__ float p[128];
    __shared__ float red[128];
    int b = blockIdx.x >> 2, hc = blockIdx.x & 3;
    int tid = threadIdx.x;

    if (tid < 128) {
        float v = g_sc[b * SS + tid];
        p[tid] = v;
        red[tid] = v;
    }
    __syncthreads();
    for (int o = 64; o > 0; o >>= 1) {
        if (tid < o) red[tid] = fmaxf(red[tid], red[tid + o]);
        __syncthreads();
    }
    float mx = red[0];
    __syncthreads();
    if (tid < 128) {
        float e = expf(p[tid] - mx);
        p[tid] = e;
        red[tid] = e;
    }
    __syncthreads();
    for (int o = 64; o > 0; o >>= 1) {
        if (tid < o) red[tid] += red[tid + o];
        __syncthreads();
    }
    float inv = 1.f / red[0];
    __syncthreads();
    if (tid < 128) p[tid] *= inv;
    __syncthreads();

    int dim = hc * 192 + tid;
    float acc = 0.f;
    const float* ep = enc + (b * SS) * HH + dim;
#pragma unroll 8
    for (int s = 0; s < SS; s++) acc += p[s] * ep[s * HH];
    g_ctx[b * HH + dim] = acc;
}

// ---------------- carry update ----------------------------------------------
#define ATTH_SMEM ((768 * 32 + 6 * 1536 + 24 * 32) * 4)
__global__ void k_atth2(const float* __restrict__ Wctx,
                        const float* __restrict__ bctx, int t) {
    extern __shared__ float sm[];
    float* in_s = sm;
    float* w_s = sm + 768 * 32;
    float* red = w_s + 6 * 1536;
    int tid = threadIdx.x;
    int j0 = blockIdx.x * 6;

    for (int i = tid; i < 2304; i += 768) {
        int row = i / 384, c4 = i % 384;
        *(float4*)(w_s + row * 1536 + c4 * 4) =
            *(const float4*)(Wctx + (j0 + row) * (2 * HH) + c4 * 4);
    }

    int b = tid & 31, q = tid >> 5;
    int jl = q % 6, sub = q / 6;
    float acc = 0.f;
#pragma unroll
    for (int ph = 0; ph < 2; ph++) {
        const float* src = ph ? (g_Hbuf + (t * BB) * HH) : g_ctx;
        __syncthreads();
        for (int i = tid; i < 6144; i += 768) {
            int bb = i & 31, kq = i >> 5;
            float4 v = *(const float4*)(src + bb * HH + kq * 4);
            in_s[(kq * 4 + 0) * 32 + bb] = v.x;
            in_s[(kq * 4 + 1) * 32 + bb] = v.y;
            in_s[(kq * 4 + 2) * 32 + bb] = v.z;
            in_s[(kq * 4 + 3) * 32 + bb] = v.w;
        }
        __syncthreads();
        const float4* wp = (const float4*)(w_s + jl * 1536 + ph * 768 + sub * 192);
        const float* ip = in_s + sub * 192 * 32 + b;
#pragma unroll 8
        for (int c = 0; c < 48; c++) {
            float4 v = wp[c];
            float h0 = ip[c * 128 + 0], h1 = ip[c * 128 + 32];
            float h2 = ip[c * 128 + 64], h3 = ip[c * 128 + 96];
            acc += h0 * v.x + h1 * v.y + h2 * v.z + h3 * v.w;
        }
    }
    red[q * 32 + b] = acc;
    __syncthreads();
    if (tid < 192) {
        int b2 = tid & 31, j2 = tid >> 5, j = j0 + j2;
        float s = 0.f;
#pragma unroll
        for (int qq = 0; qq < 4; qq++) s += red[(qq * 6 + j2) * 32 + b2];
        g_h[b2 * HH + j] = tanhf(s + bctx[j]);
    }
}

// ---------------- bf16 split conversions ------------------------------------
__device__ __forceinline__ void split4(float4 v, __nv_bfloat16* hi,
                                       __nv_bfloat16* lo) {
    float f[4];
    f[0] = v.x; f[1] = v.y; f[2] = v.z; f[3] = v.w;
#pragma unroll
    for (int i = 0; i < 4; i++) {
        __nv_bfloat16 h = __float2bfloat16_rn(f[i]);
        hi[i] = h;
        lo[i] = __float2bfloat16_rn(f[i] - __bfloat162float(h));
    }
}

// B' = [Bh | Bl | Bh], rows padded to VPAD with zeros
__global__ void k_cvtB(const float* __restrict__ Wp) {
    long idx = (long)blockIdx.x * blockDim.x + threadIdx.x;
    if (idx >= (long)VPAD * 192) return;
    int row = (int)(idx / 192), c4 = (int)(idx % 192);
    float4 v = (row < VV) ? *(const float4*)(Wp + (long)row * HH + c4 * 4)
                          : make_float4(0.f, 0.f, 0.f, 0.f);
    __nv_bfloat16 hi[4], lo[4];
    split4(v, hi, lo);
    __nv_bfloat16* dst = g_Bs + (long)row * KS + c4 * 4;
    *(uint2*)(dst) = *(uint2*)hi;
    *(uint2*)(dst + HH) = *(uint2*)lo;
    *(uint2*)(dst + 2 * HH) = *(uint2*)hi;
}

// A' = [Ah | Ah | Al]
__global__ void k_cvtA() {
    int idx = blockIdx.x * blockDim.x + threadIdx.x;
    if (idx >= TT * BB * 192) return;
    int row = idx / 192, c4 = idx % 192;
    float4 v = *(const float4*)(g_Hbuf + row * HH + c4 * 4);
    __nv_bfloat16 hi[4], lo[4];
    split4(v, hi, lo);
    __nv_bfloat16* dst = g_As + row * KS + c4 * 4;
    *(uint2*)(dst) = *(uint2*)hi;
    *(uint2*)(dst + HH) = *(uint2*)hi;
    *(uint2*)(dst + 2 * HH) = *(uint2*)lo;
}

// ---------------- logits GEMM on tensor cores (mma.sync bf16) ----------------
#define LDP 40  // padded smem row length in bf16 (80 bytes)
__global__ void __launch_bounds__(256)
k_predmma(const float* __restrict__ bp, float* __restrict__ out) {
    __shared__ __nv_bfloat16 sA[2][128 * LDP];
    __shared__ __nv_bfloat16 sB[2][128 * LDP];

    int tid = threadIdx.x;
    int lane = tid & 31, wid = tid >> 5;
    int m0 = blockIdx.x * 128, n0 = blockIdx.y * 128;
    int warp_m = (wid >> 1) * 32;
    int warp_n = (wid & 1) * 64;

    const __nv_bfloat16* gA = g_As + (long)m0 * KS;
    const __nv_bfloat16* gB = g_Bs + (long)n0 * KS;

    float acc[2][8][4];
#pragma unroll
    for (int i = 0; i < 2; i++)
#pragma unroll
        for (int j = 0; j < 8; j++)
#pragma unroll
            for (int r = 0; r < 4; r++) acc[i][j][r] = 0.f;

    int ar0 = tid >> 2, ac0 = (tid & 3) * 8;
    int ar1 = (tid + 256) >> 2, ac1 = ((tid + 256) & 3) * 8;

    u32 sA0 = (u32)__cvta_generic_to_shared(&sA[0][0]);
    u32 sB0 = (u32)__cvta_generic_to_shared(&sB[0][0]);
    const u32 stageA = 128 * LDP * 2;
    const u32 stageB = 128 * LDP * 2;

    cp_async16(sA0 + (ar0 * LDP + ac0) * 2, gA + (long)ar0 * KS + ac0);
    cp_async16(sA0 + (ar1 * LDP + ac1) * 2, gA + (long)ar1 * KS + ac1);
    cp_async16(sB0 + (ar0 * LDP + ac0) * 2, gB + (long)ar0 * KS + ac0);
    cp_async16(sB0 + (ar1 * LDP + ac1) * 2, gB + (long)ar1 * KS + ac1);
    cp_commit();

    const int NIT = KS / 32;  // 72
    for (int it = 0; it < NIT; it++) {
        int buf = it & 1;
        if (it + 1 < NIT) {
            int k0 = (it + 1) * 32;
            u32 dA = sA0 + (buf ^ 1) * stageA;
            u32 dB = sB0 + (buf ^ 1) * stageB;
            cp_async16(dA + (ar0 * LDP + ac0) * 2, gA + (long)ar0 * KS + k0 + ac0);
            cp_async16(dA + (ar1 * LDP + ac1) * 2, gA + (long)ar1 * KS + k0 + ac1);
            cp_async16(dB + (ar0 * LDP + ac0) * 2, gB + (long)ar0 * KS + k0 + ac0);
            cp_async16(dB + (ar1 * LDP + ac1) * 2, gB + (long)ar1 * KS + k0 + ac1);
            cp_commit();
            cp_wait<1>();
        } else {
            cp_wait<0>();
        }
        __syncthreads();

        u32 baseA = sA0 + buf * stageA;
        u32 baseB = sB0 + buf * stageB;
#pragma unroll
        for (int ks = 0; ks < 2; ks++) {
            u32 areg[2][4];
#pragma unroll
            for (int mi = 0; mi < 2; mi++) {
                u32 addr = baseA +
                    ((warp_m + mi * 16 + (lane & 15)) * LDP +
                     ks * 16 + (lane >> 4) * 8) * 2;
                ldsm_x4(areg[mi][0], areg[mi][1], areg[mi][2], areg[mi][3],
                        addr);
            }
            u32 breg[4][4];
#pragma unroll
            for (int np = 0; np < 4; np++) {
                u32 addr = baseB +
                    ((warp_n + np * 16 + (lane & 15)) * LDP +
                     ks * 16 + (lane >> 4) * 8) * 2;
                ldsm_x4(breg[np][0], breg[np][1], breg[np][2], breg[np][3],
                        addr);
            }
#pragma unroll
            for (int mi = 0; mi < 2; mi++) {
#pragma unroll
                for (int nf = 0; nf < 8; nf++) {
                    int np = nf >> 1;
                    u32 b0 = (nf & 1) ? breg[np][1] : breg[np][0];
                    u32 b1 = (nf & 1) ? breg[np][3] : breg[np][2];
                    mma_bf16_16816(acc[mi][nf][0], acc[mi][nf][1],
                                   acc[mi][nf][2], acc[mi][nf][3],
                                   areg[mi][0], areg[mi][1], areg[mi][2],
                                   areg[mi][3], b0, b1);
                }
            }
        }
        __syncthreads();
    }

#pragma unroll
    for (int mi = 0; mi < 2; mi++) {
        int mA = m0 + warp_m + mi * 16 + (lane >> 2);
#pragma unroll
        for (int half = 0; half < 2; half++) {
            int m = mA + half * 8;
            int t = m >> 5, bb = m & 31;
            float* orow = out + (long)(bb * TT + t) * VV;
#pragma unroll
            for (int nf = 0; nf < 8; nf++) {
                int n = n0 + warp_n + nf * 8 + (lane & 3) * 2;
                if (n < VV) {
                    float2 bias = *(const float2*)(bp + n);
                    float2 v;
                    v.x = acc[mi][nf][half * 2 + 0] + bias.x;
                    v.y = acc[mi][nf][half * 2 + 1] + bias.y;
                    *(float2*)(orow + n) = v;
                }
            }
        }
    }
}

// ---------------- launcher ---------------------------------------------------
extern "C" void kernel_launch(void* const* d_in, const int* in_sizes, int n_in,
                              void* d_out, int out_size) {
    const float* x    = (const float*)d_in[0];
    const float* h0   = (const float*)d_in[1];
    const float* enc  = (const float*)d_in[2];
    const float* Wih  = (const float*)d_in[3];
    const float* Whh  = (const float*)d_in[4];
    const float* bih  = (const float*)d_in[5];
    const float* bhh  = (const float*)d_in[6];
    const float* Wp   = (const float*)d_in[7];
    const float* bp   = (const float*)d_in[8];
    const float* Watt = (const float*)d_in[9];
    const float* batt = (const float*)d_in[10];
    const float* Wctx = (const float*)d_in[11];
    const float* bctx = (const float*)d_in[12];
    float* out = (float*)d_out;

    cudaFuncSetAttribute(k_gru2, cudaFuncAttributeMaxDynamicSharedMemorySize,
                         GRU_SMEM);
    cudaFuncSetAttribute(k_atth2, cudaFuncAttributeMaxDynamicSharedMemorySize,
                         ATTH_SMEM);

    k_prolog<<<PROLOG_BLOCKS, 256>>>(x, Wih, bih, enc, Watt, batt, h0);
    k_cvtB<<<(VPAD * 192 + 255) / 256, 256>>>(Wp);

    for (int t = 0; t < TT; t++) {
        k_gru2<<<128, 768, GRU_SMEM>>>(Whh, bhh, t);
        k_score<<<BB * 8, 256>>>(t);
        k_ctx<<<BB * 4, 192>>>(enc, t);
        k_atth2<<<128, 768, ATTH_SMEM>>>(Wctx, bctx, t);
    }

    k_cvtA<<<(TT * BB * 192 + 255) / 256, 256>>>();
    k_predmma<<<dim3((TT * BB) / 128, VPAD / 128), 256>>>(bp, out);
}

// round 14
// speedup vs baseline: 1.5827x; 1.0626x over previous
#include <cuda_runtime.h>
#include <cuda_bf16.h>
#include <cstdint>
#include <math.h>

typedef unsigned int u32;

#define BB 32
#define TT 48
#define DD 768
#define HH 768
#define SS 128
#define VV 28996
#define H3 2304
#define VPAD 29056           // 227 * 128
#define KS 2304              // split-K: [hi | hi/lo | lo/hi]

// ---------------- scratch (static device globals; no allocation) -------------
__device__ float g_GI[TT * BB * H3];
__device__ float g_Hbuf[TT * BB * HH];
__device__ float g_hT[HH * BB];                // carry h, TRANSPOSED [k][b]
__device__ float g_hgT[HH * BB];               // current-step GRU out, transposed
__device__ float g_ctxT[HH * BB];              // attention ctx, transposed
__device__ float g_E[BB * SS * HH];
__device__ float g_e0[BB * SS];
__device__ float g_sc[BB * SS];                // raw attention scores
__device__ __nv_bfloat16 g_As[TT * BB * KS];   // A' = [Ah | Ah | Al]
__device__ __nv_bfloat16 g_Bs[VPAD * KS];      // B' = [Bh | Bl | Bh]

// ---------------- PTX helpers (lvalue-safe wrappers) -------------------------
__device__ __forceinline__ void ldsm_x4(u32& r0, u32& r1, u32& r2, u32& r3,
                                        u32 addr) {
    asm volatile(
        "ldmatrix.sync.aligned.m8n8.x4.shared.b16 {%0,%1,%2,%3}, [%4];"
        : "=r"(r0), "=r"(r1), "=r"(r2), "=r"(r3)
        : "r"(addr));
}

__device__ __forceinline__ void mma_bf16_16816(float& c0, float& c1,
                                               float& c2, float& c3,
                                               u32 a0, u32 a1, u32 a2, u32 a3,
                                               u32 b0, u32 b1) {
    asm volatile(
        "mma.sync.aligned.m16n8k16.row.col.f32.bf16.bf16.f32 "
        "{%0,%1,%2,%3}, {%4,%5,%6,%7}, {%8,%9}, {%0,%1,%2,%3};"
        : "+f"(c0), "+f"(c1), "+f"(c2), "+f"(c3)
        : "r"(a0), "r"(a1), "r"(a2), "r"(a3), "r"(b0), "r"(b1));
}

__device__ __forceinline__ void cp_async16(u32 dst, const void* src) {
    asm volatile("cp.async.cg.shared.global [%0], [%1], 16;\n" ::"r"(dst),
                 "l"(src));
}

__device__ __forceinline__ void cp_commit() {
    asm volatile("cp.async.commit_group;\n");
}

template <int N>
__device__ __forceinline__ void cp_wait() {
    asm volatile("cp.async.wait_group %0;\n" ::"n"(N));
}

// ---------------- fused prologue ---------------------------------------------
// blocks [0,96): init_hT | [96,960): GI gemm | [960,1728): E gemm | rest: e0
#define PROLOG_BLOCKS 1856
__global__ void __launch_bounds__(256)
k_prolog(const float* __restrict__ x, const float* __restrict__ Wih,
         const float* __restrict__ bih, const float* __restrict__ enc,
         const float* __restrict__ Watt, const float* __restrict__ batt,
         const float* __restrict__ hs) {
    __shared__ float as[16][68];
    __shared__ float bs[16][68];
    int bid = blockIdx.x;
    int tid = threadIdx.x;

    if (bid < 96) {
        int i = bid * 256 + tid;
        int b = i / HH, j = i % HH;
        g_hT[j * BB + b] = hs[i];
        return;
    }
    if (bid < 960) {
        int id = bid - 96;
        int n0 = (id % 36) * 64, m0 = (id / 36) * 64;
        int tx = tid & 15, ty = tid >> 4;
        int lm = tid >> 2, lk = (tid & 3) * 4;

        int gm = m0 + lm;
        const float* aptr = x + ((gm & 31) * TT + (gm >> 5)) * DD;
        const float* bptr = Wih + (n0 + lm) * DD;

        float acc[4][4];
#pragma unroll
        for (int i = 0; i < 4; i++)
#pragma unroll
            for (int j = 0; j < 4; j++) acc[i][j] = 0.f;

        for (int k0 = 0; k0 < DD; k0 += 16) {
            float4 av = *(const float4*)(aptr + k0 + lk);
            float4 bv = *(const float4*)(bptr + k0 + lk);
            as[lk + 0][lm] = av.x; as[lk + 1][lm] = av.y;
            as[lk + 2][lm] = av.z; as[lk + 3][lm] = av.w;
            bs[lk + 0][lm] = bv.x; bs[lk + 1][lm] = bv.y;
            bs[lk + 2][lm] = bv.z; bs[lk + 3][lm] = bv.w;
            __syncthreads();
#pragma unroll
            for (int kk = 0; kk < 16; kk++) {
                float4 a4 = *(const float4*)&as[kk][ty * 4];
                float4 b4 = *(const float4*)&bs[kk][tx * 4];
                acc[0][0] += a4.x * b4.x; acc[0][1] += a4.x * b4.y;
                acc[0][2] += a4.x * b4.z; acc[0][3] += a4.x * b4.w;
                acc[1][0] += a4.y * b4.x; acc[1][1] += a4.y * b4.y;
                acc[1][2] += a4.y * b4.z; acc[1][3] += a4.y * b4.w;
                acc[2][0] += a4.z * b4.x; acc[2][1] += a4.z * b4.y;
                acc[2][2] += a4.z * b4.z; acc[2][3] += a4.z * b4.w;
                acc[3][0] += a4.w * b4.x; acc[3][1] += a4.w * b4.y;
                acc[3][2] += a4.w * b4.z; acc[3][3] += a4.w * b4.w;
            }
            __syncthreads();
        }
#pragma unroll
        for (int i = 0; i < 4; i++) {
            int m = m0 + ty * 4 + i;
#pragma unroll
            for (int j = 0; j < 4; j++) {
                int n = n0 + tx * 4 + j;
                g_GI[m * H3 + n] = acc[i][j] + bih[n];
            }
        }
        return;
    }
    if (bid < 1728) {
        int id = bid - 960;
        int n0 = (id % 12) * 64, m0 = (id / 12) * 64;
        int tx = tid & 15, ty = tid >> 4;
        int lm = tid >> 2, lk = (tid & 3) * 4;
        int lr = tid >> 4, lc = (tid & 15) * 4;

        const float* aptr = enc + (m0 + lm) * HH;

        float acc[4][4];
#pragma unroll
        for (int i = 0; i < 4; i++)
#pragma unroll
            for (int j = 0; j < 4; j++) acc[i][j] = 0.f;

        for (int k0 = 0; k0 < HH; k0 += 16) {
            float4 av = *(const float4*)(aptr + k0 + lk);
            float4 bv = *(const float4*)(Watt + (k0 + lr) * HH + n0 + lc);
            as[lk + 0][lm] = av.x; as[lk + 1][lm] = av.y;
            as[lk + 2][lm] = av.z; as[lk + 3][lm] = av.w;
            *(float4*)&bs[lr][lc] = bv;
            __syncthreads();
#pragma unroll
            for (int kk = 0; kk < 16; kk++) {
                float4 a4 = *(const float4*)&as[kk][ty * 4];
                float4 b4 = *(const float4*)&bs[kk][tx * 4];
                acc[0][0] += a4.x * b4.x; acc[0][1] += a4.x * b4.y;
                acc[0][2] += a4.x * b4.z; acc[0][3] += a4.x * b4.w;
                acc[1][0] += a4.y * b4.x; acc[1][1] += a4.y * b4.y;
                acc[1][2] += a4.y * b4.z; acc[1][3] += a4.y * b4.w;
                acc[2][0] += a4.z * b4.x; acc[2][1] += a4.z * b4.y;
                acc[2][2] += a4.z * b4.z; acc[2][3] += a4.z * b4.w;
                acc[3][0] += a4.w * b4.x; acc[3][1] += a4.w * b4.y;
                acc[3][2] += a4.w * b4.z; acc[3][3] += a4.w * b4.w;
            }
            __syncthreads();
        }
#pragma unroll
        for (int i = 0; i < 4; i++) {
            int m = m0 + ty * 4 + i;
#pragma unroll
            for (int j = 0; j < 4; j++) {
                g_E[m * HH + n0 + tx * 4 + j] = acc[i][j];
            }
        }
        return;
    }
    {
        int id = bid - 1728;
        int gw = id * 8 + (tid >> 5);
        int lane = tid & 31;
        for (int r = gw; r < BB * SS; r += 1024) {
            const float4* e4 = (const float4*)(enc + r * HH);
            const float4* b4 = (const float4*)batt;
            float s = 0.f;
#pragma unroll
            for (int c = 0; c < 6; c++) {
                float4 ev = e4[c * 32 + lane];
                float4 bv = b4[c * 32 + lane];
                s += ev.x * bv.x + ev.y * bv.y + ev.z * bv.z + ev.w * bv.w;
            }
#pragma unroll
            for (int o = 16; o > 0; o >>= 1)
                s += __shfl_down_sync(0xffffffffu, s, o);
            if (lane == 0) g_e0[r] = s;
        }
    }
}

// ---------------- GRU step: reads g_hT directly (no smem staging) ------------
// smem: w_s[18*768] + red[3*24*32] = 64.5 KB
#define GRU_SMEM ((18 * 768 + 3 * 24 * 32) * 4)
__global__ void k_gru2(const float* __restrict__ Whh,
                       const float* __restrict__ bhh, int t) {
    extern __shared__ float sm[];
    float* w_s = sm;
    float* red = w_s + 18 * 768;
    int tid = threadIdx.x;
    int j0 = blockIdx.x * 6;

    for (int i = tid; i < 3456; i += 768) {
        int row = i / 192, c4 = i % 192;
        int g = row / 6, jl = row % 6;
        *(float4*)(w_s + row * 768 + c4 * 4) =
            *(const float4*)(Whh + (g * HH + j0 + jl) * HH + c4 * 4);
    }
    __syncthreads();

    int b = tid & 31, q = tid >> 5;
    int jl = q % 6, qt = q / 6;
    int kbeg = qt * 192;
    const float4* w0 = (const float4*)(w_s + (0 + jl) * 768 + kbeg);
    const float4* w1 = (const float4*)(w_s + (6 + jl) * 768 + kbeg);
    const float4* w2 = (const float4*)(w_s + (12 + jl) * 768 + kbeg);
    const float* hp = g_hT + kbeg * 32 + b;     // [k][b] coalesced across lanes
    float a0 = 0.f, a1 = 0.f, a2 = 0.f;
#pragma unroll 8
    for (int c = 0; c < 48; c++) {
        float4 v0 = w0[c], v1 = w1[c], v2 = w2[c];
        float h0 = hp[c * 128 + 0], h1 = hp[c * 128 + 32];
        float h2 = hp[c * 128 + 64], h3 = hp[c * 128 + 96];
        a0 += h0 * v0.x + h1 * v0.y + h2 * v0.z + h3 * v0.w;
        a1 += h0 * v1.x + h1 * v1.y + h2 * v1.z + h3 * v1.w;
        a2 += h0 * v2.x + h1 * v2.y + h2 * v2.z + h3 * v2.w;
    }
    red[(0 * 24 + q) * 32 + b] = a0;
    red[(1 * 24 + q) * 32 + b] = a1;
    red[(2 * 24 + q) * 32 + b] = a2;
    __syncthreads();

    if (tid < 192) {
        int b2 = tid & 31, j2 = tid >> 5, j = j0 + j2;
        float ar = 0.f, az = 0.f, an = 0.f;
#pragma unroll
        for (int qq = 0; qq < 4; qq++) {
            int q2 = qq * 6 + j2;
            ar += red[(0 * 24 + q2) * 32 + b2];
            az += red[(1 * 24 + q2) * 32 + b2];
            an += red[(2 * 24 + q2) * 32 + b2];
        }
        const float* gi = g_GI + (t * BB + b2) * H3;
        float r = 1.f / (1.f + expf(-(gi[j] + ar + bhh[j])));
        float z = 1.f / (1.f + expf(-(gi[HH + j] + az + bhh[HH + j])));
        float n = tanhf(gi[2 * HH + j] + r * (an + bhh[2 * HH + j]));
        float hprev = g_hT[j * 32 + b2];
        float hnew = (1.f - z) * n + z * hprev;
        g_Hbuf[(t * BB + b2) * HH + j] = hnew;  // for score / cvtA
        g_hgT[j * 32 + b2] = hnew;              // transposed, for atth2
    }
}

// ---------------- scores: g_sc[b][s] = h . E[b,s] + e0  (256 blocks) ---------
__global__ void __launch_bounds__(256)
k_score(int t) {
    __shared__ __align__(16) float hg[768];
    int b = blockIdx.x >> 3, sc = blockIdx.x & 7;
    int tid = threadIdx.x;

    for (int i = tid; i < 768; i += 256) hg[i] = g_Hbuf[(t * BB + b) * HH + i];
    __syncthreads();

    int w = tid >> 5, lane = tid & 31;
    const float4* hg4 = (const float4*)hg;
#pragma unroll
    for (int i = 0; i < 2; i++) {
        int s = sc * 16 + w * 2 + i;
        const float4* e4 = (const float4*)(g_E + (b * SS + s) * HH);
        float d = 0.f;
#pragma unroll
        for (int c = 0; c < 6; c++) {
            float4 ev = e4[c * 32 + lane];
            float4 hv = hg4[c * 32 + lane];
            d += ev.x * hv.x + ev.y * hv.y + ev.z * hv.z + ev.w * hv.w;
        }
#pragma unroll
        for (int o = 16; o > 0; o >>= 1) d += __shfl_down_sync(0xffffffffu, d, o);
        if (lane == 0) g_sc[b * SS + s] = d + g_e0[b * SS + s];
    }
}

// ---------------- ctx: softmax (per block) + weighted sum, writes ctxT -------
// grid 128 = 32 b x 4 dim-chunks of 192; 192 threads, unroll 8.
__global__ void __launch_bounds__(192)
k_ctx(const float* __restrict__ enc, int t) {
    __shared__ float p[128];
    __shared__ float red[128];
    int b = blockIdx.x >> 2, hc = blockIdx.x & 3;
    int tid = threadIdx.x;

    if (tid < 128) {
        float v = g_sc[b * SS + tid];
        p[tid] = v;
        red[tid] = v;
    }
    __syncthreads();
    for (int o = 64; o > 0; o >>= 1) {
        if (tid < o) red[tid] = fmaxf(red[tid], red[tid + o]);
        __syncthreads();
    }
    float mx = red[0];
    __syncthreads();
    if (tid < 128) {
        float e = expf(p[tid] - mx);
        p[tid] = e;
        red[tid] = e;
    }
    __syncthreads();
    for (int o = 64; o > 0; o >>= 1) {
        if (tid < o) red[tid] += red[tid + o];
        __syncthreads();
    }
    float inv = 1.f / red[0];
    __syncthreads();
    if (tid < 128) p[tid] *= inv;
    __syncthreads();

    int dim = hc * 192 + tid;
    float acc = 0.f;
    const float* ep = enc + (b * SS) * HH + dim;
#pragma unroll 8
    for (int s = 0; s < SS; s++) acc += p[s] * ep[s * HH];
    g_ctxT[dim * 32 + b] = acc;                 // transposed, for atth2
}

// ---------------- carry update: reads ctxT/hgT directly ----------------------
// smem: w_s[6*1536] + red[24*32] = 40 KB
#define ATTH_SMEM ((6 * 1536 + 24 * 32) * 4)
__global__ void k_atth2(const float* __restrict__ Wctx,
                        const float* __restrict__ bctx, int t) {
    extern __shared__ float sm[];
    float* w_s = sm;
    float* red = w_s + 6 * 1536;
    int tid = threadIdx.x;
    int j0 = blockIdx.x * 6;

    for (int i = tid; i < 2304; i += 768) {
        int row = i / 384, c4 = i % 384;
        *(float4*)(w_s + row * 1536 + c4 * 4) =
            *(const float4*)(Wctx + (j0 + row) * (2 * HH) + c4 * 4);
    }
    __syncthreads();

    int b = tid & 31, q = tid >> 5;
    int jl = q % 6, sub = q / 6;
    float acc = 0.f;
#pragma unroll
    for (int ph = 0; ph < 2; ph++) {
        const float* ip =
            (ph ? g_hgT : g_ctxT) + sub * 192 * 32 + b;
        const float4* wp = (const float4*)(w_s + jl * 1536 + ph * 768 + sub * 192);
#pragma unroll 8
        for (int c = 0; c < 48; c++) {
            float4 v = wp[c];
            float h0 = ip[c * 128 + 0], h1 = ip[c * 128 + 32];
            float h2 = ip[c * 128 + 64], h3 = ip[c * 128 + 96];
            acc += h0 * v.x + h1 * v.y + h2 * v.z + h3 * v.w;
        }
    }
    red[q * 32 + b] = acc;
    __syncthreads();
    if (tid < 192) {
        int b2 = tid & 31, j2 = tid >> 5, j = j0 + j2;
        float s = 0.f;
#pragma unroll
        for (int qq = 0; qq < 4; qq++) s += red[(qq * 6 + j2) * 32 + b2];
        g_hT[j * 32 + b2] = tanhf(s + bctx[j]);
    }
}

// ---------------- bf16 split conversions ------------------------------------
__device__ __forceinline__ void split4(float4 v, __nv_bfloat16* hi,
                                       __nv_bfloat16* lo) {
    float f[4];
    f[0] = v.x; f[1] = v.y; f[2] = v.z; f[3] = v.w;
#pragma unroll
    for (int i = 0; i < 4; i++) {
        __nv_bfloat16 h = __float2bfloat16_rn(f[i]);
        hi[i] = h;
        lo[i] = __float2bfloat16_rn(f[i] - __bfloat162float(h));
    }
}

// B' = [Bh | Bl | Bh], rows padded to VPAD with zeros
__global__ void k_cvtB(const float* __restrict__ Wp) {
    long idx = (long)blockIdx.x * blockDim.x + threadIdx.x;
    if (idx >= (long)VPAD * 192) return;
    int row = (int)(idx / 192), c4 = (int)(idx % 192);
    float4 v = (row < VV) ? *(const float4*)(Wp + (long)row * HH + c4 * 4)
                          : make_float4(0.f, 0.f, 0.f, 0.f);
    __nv_bfloat16 hi[4], lo[4];
    split4(v, hi, lo);
    __nv_bfloat16* dst = g_Bs + (long)row * KS + c4 * 4;
    *(uint2*)(dst) = *(uint2*)hi;
    *(uint2*)(dst + HH) = *(uint2*)lo;
    *(uint2*)(dst + 2 * HH) = *(uint2*)hi;
}

// A' = [Ah | Ah | Al]
__global__ void k_cvtA() {
    int idx = blockIdx.x * blockDim.x + threadIdx.x;
    if (idx >= TT * BB * 192) return;
    int row = idx / 192, c4 = idx % 192;
    float4 v = *(const float4*)(g_Hbuf + row * HH + c4 * 4);
    __nv_bfloat16 hi[4], lo[4];
    split4(v, hi, lo);
    __nv_bfloat16* dst = g_As + row * KS + c4 * 4;
    *(uint2*)(dst) = *(uint2*)hi;
    *(uint2*)(dst + HH) = *(uint2*)hi;
    *(uint2*)(dst + 2 * HH) = *(uint2*)lo;
}

// ---------------- logits GEMM on tensor cores (mma.sync bf16) ----------------
#define LDP 40  // padded smem row length in bf16 (80 bytes)
__global__ void __launch_bounds__(256)
k_predmma(const float* __restrict__ bp, float* __restrict__ out) {
    __shared__ __nv_bfloat16 sA[2][128 * LDP];
    __shared__ __nv_bfloat16 sB[2][128 * LDP];

    int tid = threadIdx.x;
    int lane = tid & 31, wid = tid >> 5;
    int m0 = blockIdx.x * 128, n0 = blockIdx.y * 128;
    int warp_m = (wid >> 1) * 32;
    int warp_n = (wid & 1) * 64;

    const __nv_bfloat16* gA = g_As + (long)m0 * KS;
    const __nv_bfloat16* gB = g_Bs + (long)n0 * KS;

    float acc[2][8][4];
#pragma unroll
    for (int i = 0; i < 2; i++)
#pragma unroll
        for (int j = 0; j < 8; j++)
#pragma unroll
            for (int r = 0; r < 4; r++) acc[i][j][r] = 0.f;

    int ar0 = tid >> 2, ac0 = (tid & 3) * 8;
    int ar1 = (tid + 256) >> 2, ac1 = ((tid + 256) & 3) * 8;

    u32 sA0 = (u32)__cvta_generic_to_shared(&sA[0][0]);
    u32 sB0 = (u32)__cvta_generic_to_shared(&sB[0][0]);
    const u32 stageA = 128 * LDP * 2;
    const u32 stageB = 128 * LDP * 2;

    cp_async16(sA0 + (ar0 * LDP + ac0) * 2, gA + (long)ar0 * KS + ac0);
    cp_async16(sA0 + (ar1 * LDP + ac1) * 2, gA + (long)ar1 * KS + ac1);
    cp_async16(sB0 + (ar0 * LDP + ac0) * 2, gB + (long)ar0 * KS + ac0);
    cp_async16(sB0 + (ar1 * LDP + ac1) * 2, gB + (long)ar1 * KS + ac1);
    cp_commit();

    const int NIT = KS / 32;  // 72
    for (int it = 0; it < NIT; it++) {
        int buf = it & 1;
        if (it + 1 < NIT) {
            int k0 = (it + 1) * 32;
            u32 dA = sA0 + (buf ^ 1) * stageA;
            u32 dB = sB0 + (buf ^ 1) * stageB;
            cp_async16(dA + (ar0 * LDP + ac0) * 2, gA + (long)ar0 * KS + k0 + ac0);
            cp_async16(dA + (ar1 * LDP + ac1) * 2, gA + (long)ar1 * KS + k0 + ac1);
            cp_async16(dB + (ar0 * LDP + ac0) * 2, gB + (long)ar0 * KS + k0 + ac0);
            cp_async16(dB + (ar1 * LDP + ac1) * 2, gB + (long)ar1 * KS + k0 + ac1);
            cp_commit();
            cp_wait<1>();
        } else {
            cp_wait<0>();
        }
        __syncthreads();

        u32 baseA = sA0 + buf * stageA;
        u32 baseB = sB0 + buf * stageB;
#pragma unroll
        for (int ks = 0; ks < 2; ks++) {
            u32 areg[2][4];
#pragma unroll
            for (int mi = 0; mi < 2; mi++) {
                u32 addr = baseA +
                    ((warp_m + mi * 16 + (lane & 15)) * LDP +
                     ks * 16 + (lane >> 4) * 8) * 2;
                ldsm_x4(areg[mi][0], areg[mi][1], areg[mi][2], areg[mi][3],
                        addr);
            }
            u32 breg[4][4];
#pragma unroll
            for (int np = 0; np < 4; np++) {
                u32 addr = baseB +
                    ((warp_n + np * 16 + (lane & 15)) * LDP +
                     ks * 16 + (lane >> 4) * 8) * 2;
                ldsm_x4(breg[np][0], breg[np][1], breg[np][2], breg[np][3],
                        addr);
            }
#pragma unroll
            for (int mi = 0; mi < 2; mi++) {
#pragma unroll
                for (int nf = 0; nf < 8; nf++) {
                    int np = nf >> 1;
                    u32 b0 = (nf & 1) ? breg[np][1] : breg[np][0];
                    u32 b1 = (nf & 1) ? breg[np][3] : breg[np][2];
                    mma_bf16_16816(acc[mi][nf][0], acc[mi][nf][1],
                                   acc[mi][nf][2], acc[mi][nf][3],
                                   areg[mi][0], areg[mi][1], areg[mi][2],
                                   areg[mi][3], b0, b1);
                }
            }
        }
        __syncthreads();
    }

#pragma unroll
    for (int mi = 0; mi < 2; mi++) {
        int mA = m0 + warp_m + mi * 16 + (lane >> 2);
#pragma unroll
        for (int half = 0; half < 2; half++) {
            int m = mA + half * 8;
            int t = m >> 5, bb = m & 31;
            float* orow = out + (long)(bb * TT + t) * VV;
#pragma unroll
            for (int nf = 0; nf < 8; nf++) {
                int n = n0 + warp_n + nf * 8 + (lane & 3) * 2;
                if (n < VV) {
                    float2 bias = *(const float2*)(bp + n);
                    float2 v;
                    v.x = acc[mi][nf][half * 2 + 0] + bias.x;
                    v.y = acc[mi][nf][half * 2 + 1] + bias.y;
                    *(float2*)(orow + n) = v;
                }
            }
        }
    }
}

// ---------------- launcher ---------------------------------------------------
extern "C" void kernel_launch(void* const* d_in, const int* in_sizes, int n_in,
                              void* d_out, int out_size) {
    const float* x    = (const float*)d_in[0];
    const float* h0   = (const float*)d_in[1];
    const float* enc  = (const float*)d_in[2];
    const float* Wih  = (const float*)d_in[3];
    const float* Whh  = (const float*)d_in[4];
    const float* bih  = (const float*)d_in[5];
    const float* bhh  = (const float*)d_in[6];
    const float* Wp   = (const float*)d_in[7];
    const float* bp   = (const float*)d_in[8];
    const float* Watt = (const float*)d_in[9];
    const float* batt = (const float*)d_in[10];
    const float* Wctx = (const float*)d_in[11];
    const float* bctx = (const float*)d_in[12];
    float* out = (float*)d_out;

    cudaFuncSetAttribute(k_gru2, cudaFuncAttributeMaxDynamicSharedMemorySize,
                         GRU_SMEM);
    cudaFuncSetAttribute(k_atth2, cudaFuncAttributeMaxDynamicSharedMemorySize,
                         ATTH_SMEM);

    k_prolog<<<PROLOG_BLOCKS, 256>>>(x, Wih, bih, enc, Watt, batt, h0);
    k_cvtB<<<(VPAD * 192 + 255) / 256, 256>>>(Wp);

    for (int t = 0; t < TT; t++) {
        k_gru2<<<128, 768, GRU_SMEM>>>(Whh, bhh, t);
        k_score<<<BB * 8, 256>>>(t);
        k_ctx<<<BB * 4, 192>>>(enc, t);
        k_atth2<<<128, 768, ATTH_SMEM>>>(Wctx, bctx, t);
    }

    k_cvtA<<<(TT * BB * 192 + 255) / 256, 256>>>();
    k_predmma<<<dim3((TT * BB) / 128, VPAD / 128), 256>>>(bp, out);
}

// round 15
// speedup vs baseline: 1.6200x; 1.0236x over previous
#include <cuda_runtime.h>
#include <cuda_bf16.h>
#include <cstdint>
#include <math.h>

typedef unsigned int u32;

#define BB 32
#define TT 48
#define DD 768
#define HH 768
#define SS 128
#define VV 28996
#define H3 2304
#define VPAD 29056           // 227 * 128
#define KS 2304              // split-K: [hi | hi/lo | lo/hi]

// ---------------- scratch (static device globals; no allocation) -------------
__device__ float g_GI[TT * BB * H3];
__device__ float g_Hbuf[TT * BB * HH];
__device__ float g_hT[HH * BB];                // carry h, TRANSPOSED [k][b]
__device__ float g_hgT[HH * BB];               // current-step GRU out, transposed
__device__ float g_ctxT[HH * BB];              // attention ctx, transposed
__device__ float g_E[BB * SS * HH];
__device__ float g_e0[BB * SS];
__device__ float g_sc[BB * SS];                // raw attention scores
__device__ __nv_bfloat16 g_As[TT * BB * KS];   // A' = [Ah | Ah | Al]
__device__ __nv_bfloat16 g_Bs[VPAD * KS];      // B' = [Bh | Bl | Bh]

// ---------------- PTX helpers (lvalue-safe wrappers) -------------------------
__device__ __forceinline__ void ldsm_x4(u32& r0, u32& r1, u32& r2, u32& r3,
                                        u32 addr) {
    asm volatile(
        "ldmatrix.sync.aligned.m8n8.x4.shared.b16 {%0,%1,%2,%3}, [%4];"
        : "=r"(r0), "=r"(r1), "=r"(r2), "=r"(r3)
        : "r"(addr));
}

__device__ __forceinline__ void mma_bf16_16816(float& c0, float& c1,
                                               float& c2, float& c3,
                                               u32 a0, u32 a1, u32 a2, u32 a3,
                                               u32 b0, u32 b1) {
    asm volatile(
        "mma.sync.aligned.m16n8k16.row.col.f32.bf16.bf16.f32 "
        "{%0,%1,%2,%3}, {%4,%5,%6,%7}, {%8,%9}, {%0,%1,%2,%3};"
        : "+f"(c0), "+f"(c1), "+f"(c2), "+f"(c3)
        : "r"(a0), "r"(a1), "r"(a2), "r"(a3), "r"(b0), "r"(b1));
}

__device__ __forceinline__ void cp_async16(u32 dst, const void* src) {
    asm volatile("cp.async.cg.shared.global [%0], [%1], 16;\n" ::"r"(dst),
                 "l"(src));
}

__device__ __forceinline__ void cp_commit() {
    asm volatile("cp.async.commit_group;\n");
}

template <int N>
__device__ __forceinline__ void cp_wait() {
    asm volatile("cp.async.wait_group %0;\n" ::"n"(N));
}

// ---------------- fused prologue ---------------------------------------------
// blocks [0,96): init_hT | [96,960): GI gemm | [960,1728): E gemm | rest: e0
#define PROLOG_BLOCKS 1856
__global__ void __launch_bounds__(256)
k_prolog(const float* __restrict__ x, const float* __restrict__ Wih,
         const float* __restrict__ bih, const float* __restrict__ enc,
         const float* __restrict__ Watt, const float* __restrict__ batt,
         const float* __restrict__ hs) {
    __shared__ float as[16][68];
    __shared__ float bs[16][68];
    int bid = blockIdx.x;
    int tid = threadIdx.x;

    if (bid < 96) {
        int i = bid * 256 + tid;
        int b = i / HH, j = i % HH;
        g_hT[j * BB + b] = hs[i];
        return;
    }
    if (bid < 960) {
        int id = bid - 96;
        int n0 = (id % 36) * 64, m0 = (id / 36) * 64;
        int tx = tid & 15, ty = tid >> 4;
        int lm = tid >> 2, lk = (tid & 3) * 4;

        int gm = m0 + lm;
        const float* aptr = x + ((gm & 31) * TT + (gm >> 5)) * DD;
        const float* bptr = Wih + (n0 + lm) * DD;

        float acc[4][4];
#pragma unroll
        for (int i = 0; i < 4; i++)
#pragma unroll
            for (int j = 0; j < 4; j++) acc[i][j] = 0.f;

        for (int k0 = 0; k0 < DD; k0 += 16) {
            float4 av = *(const float4*)(aptr + k0 + lk);
            float4 bv = *(const float4*)(bptr + k0 + lk);
            as[lk + 0][lm] = av.x; as[lk + 1][lm] = av.y;
            as[lk + 2][lm] = av.z; as[lk + 3][lm] = av.w;
            bs[lk + 0][lm] = bv.x; bs[lk + 1][lm] = bv.y;
            bs[lk + 2][lm] = bv.z; bs[lk + 3][lm] = bv.w;
            __syncthreads();
#pragma unroll
            for (int kk = 0; kk < 16; kk++) {
                float4 a4 = *(const float4*)&as[kk][ty * 4];
                float4 b4 = *(const float4*)&bs[kk][tx * 4];
                acc[0][0] += a4.x * b4.x; acc[0][1] += a4.x * b4.y;
                acc[0][2] += a4.x * b4.z; acc[0][3] += a4.x * b4.w;
                acc[1][0] += a4.y * b4.x; acc[1][1] += a4.y * b4.y;
                acc[1][2] += a4.y * b4.z; acc[1][3] += a4.y * b4.w;
                acc[2][0] += a4.z * b4.x; acc[2][1] += a4.z * b4.y;
                acc[2][2] += a4.z * b4.z; acc[2][3] += a4.z * b4.w;
                acc[3][0] += a4.w * b4.x; acc[3][1] += a4.w * b4.y;
                acc[3][2] += a4.w * b4.z; acc[3][3] += a4.w * b4.w;
            }
            __syncthreads();
        }
#pragma unroll
        for (int i = 0; i < 4; i++) {
            int m = m0 + ty * 4 + i;
#pragma unroll
            for (int j = 0; j < 4; j++) {
                int n = n0 + tx * 4 + j;
                g_GI[m * H3 + n] = acc[i][j] + bih[n];
            }
        }
        return;
    }
    if (bid < 1728) {
        int id = bid - 960;
        int n0 = (id % 12) * 64, m0 = (id / 12) * 64;
        int tx = tid & 15, ty = tid >> 4;
        int lm = tid >> 2, lk = (tid & 3) * 4;
        int lr = tid >> 4, lc = (tid & 15) * 4;

        const float* aptr = enc + (m0 + lm) * HH;

        float acc[4][4];
#pragma unroll
        for (int i = 0; i < 4; i++)
#pragma unroll
            for (int j = 0; j < 4; j++) acc[i][j] = 0.f;

        for (int k0 = 0; k0 < HH; k0 += 16) {
            float4 av = *(const float4*)(aptr + k0 + lk);
            float4 bv = *(const float4*)(Watt + (k0 + lr) * HH + n0 + lc);
            as[lk + 0][lm] = av.x; as[lk + 1][lm] = av.y;
            as[lk + 2][lm] = av.z; as[lk + 3][lm] = av.w;
            *(float4*)&bs[lr][lc] = bv;
            __syncthreads();
#pragma unroll
            for (int kk = 0; kk < 16; kk++) {
                float4 a4 = *(const float4*)&as[kk][ty * 4];
                float4 b4 = *(const float4*)&bs[kk][tx * 4];
                acc[0][0] += a4.x * b4.x; acc[0][1] += a4.x * b4.y;
                acc[0][2] += a4.x * b4.z; acc[0][3] += a4.x * b4.w;
                acc[1][0] += a4.y * b4.x; acc[1][1] += a4.y * b4.y;
                acc[1][2] += a4.y * b4.z; acc[1][3] += a4.y * b4.w;
                acc[2][0] += a4.z * b4.x; acc[2][1] += a4.z * b4.y;
                acc[2][2] += a4.z * b4.z; acc[2][3] += a4.z * b4.w;
                acc[3][0] += a4.w * b4.x; acc[3][1] += a4.w * b4.y;
                acc[3][2] += a4.w * b4.z; acc[3][3] += a4.w * b4.w;
            }
            __syncthreads();
        }
#pragma unroll
        for (int i = 0; i < 4; i++) {
            int m = m0 + ty * 4 + i;
#pragma unroll
            for (int j = 0; j < 4; j++) {
                g_E[m * HH + n0 + tx * 4 + j] = acc[i][j];
            }
        }
        return;
    }
    {
        int id = bid - 1728;
        int gw = id * 8 + (tid >> 5);
        int lane = tid & 31;
        for (int r = gw; r < BB * SS; r += 1024) {
            const float4* e4 = (const float4*)(enc + r * HH);
            const float4* b4 = (const float4*)batt;
            float s = 0.f;
#pragma unroll
            for (int c = 0; c < 6; c++) {
                float4 ev = e4[c * 32 + lane];
                float4 bv = b4[c * 32 + lane];
                s += ev.x * bv.x + ev.y * bv.y + ev.z * bv.z + ev.w * bv.w;
            }
#pragma unroll
            for (int o = 16; o > 0; o >>= 1)
                s += __shfl_down_sync(0xffffffffu, s, o);
            if (lane == 0) g_e0[r] = s;
        }
    }
}

// ---------------- GRU step: 256 blocks x 384 thr, j-tile 3 -------------------
// smem: w_s[9*768] + red[3*12*32] = 32.2 KB
#define GRU_SMEM ((9 * 768 + 3 * 12 * 32) * 4)
__global__ void __launch_bounds__(384)
k_gru2(const float* __restrict__ Whh, const float* __restrict__ bhh, int t) {
    extern __shared__ float sm[];
    float* w_s = sm;
    float* red = w_s + 9 * 768;
    int tid = threadIdx.x;
    int j0 = blockIdx.x * 3;

    for (int i = tid; i < 1728; i += 384) {
        int row = i / 192, c4 = i % 192;
        int g = row / 3, jl = row % 3;
        *(float4*)(w_s + row * 768 + c4 * 4) =
            *(const float4*)(Whh + (g * HH + j0 + jl) * HH + c4 * 4);
    }
    __syncthreads();

    int b = tid & 31, q = tid >> 5;          // q in 0..11
    int jl = q % 3, qt = q / 3;              // qt in 0..3
    int kbeg = qt * 192;
    const float4* w0 = (const float4*)(w_s + (0 + jl) * 768 + kbeg);
    const float4* w1 = (const float4*)(w_s + (3 + jl) * 768 + kbeg);
    const float4* w2 = (const float4*)(w_s + (6 + jl) * 768 + kbeg);
    const float* hp = g_hT + kbeg * 32 + b;
    float a0 = 0.f, a1 = 0.f, a2 = 0.f;
#pragma unroll 8
    for (int c = 0; c < 48; c++) {
        float4 v0 = w0[c], v1 = w1[c], v2 = w2[c];
        float h0 = hp[c * 128 + 0], h1 = hp[c * 128 + 32];
        float h2 = hp[c * 128 + 64], h3 = hp[c * 128 + 96];
        a0 += h0 * v0.x + h1 * v0.y + h2 * v0.z + h3 * v0.w;
        a1 += h0 * v1.x + h1 * v1.y + h2 * v1.z + h3 * v1.w;
        a2 += h0 * v2.x + h1 * v2.y + h2 * v2.z + h3 * v2.w;
    }
    red[(0 * 12 + q) * 32 + b] = a0;
    red[(1 * 12 + q) * 32 + b] = a1;
    red[(2 * 12 + q) * 32 + b] = a2;
    __syncthreads();

    if (tid < 96) {
        int b2 = tid & 31, j2 = tid >> 5, j = j0 + j2;
        float ar = 0.f, az = 0.f, an = 0.f;
#pragma unroll
        for (int qq = 0; qq < 4; qq++) {
            int q2 = qq * 3 + j2;
            ar += red[(0 * 12 + q2) * 32 + b2];
            az += red[(1 * 12 + q2) * 32 + b2];
            an += red[(2 * 12 + q2) * 32 + b2];
        }
        const float* gi = g_GI + (t * BB + b2) * H3;
        float r = 1.f / (1.f + expf(-(gi[j] + ar + bhh[j])));
        float z = 1.f / (1.f + expf(-(gi[HH + j] + az + bhh[HH + j])));
        float n = tanhf(gi[2 * HH + j] + r * (an + bhh[2 * HH + j]));
        float hprev = g_hT[j * 32 + b2];
        float hnew = (1.f - z) * n + z * hprev;
        g_Hbuf[(t * BB + b2) * HH + j] = hnew;
        g_hgT[j * 32 + b2] = hnew;
    }
}

// ---------------- scores: g_sc[b][s] = h . E[b,s] + e0  (256 blocks) ---------
__global__ void __launch_bounds__(256)
k_score(int t) {
    __shared__ __align__(16) float hg[768];
    int b = blockIdx.x >> 3, sc = blockIdx.x & 7;
    int tid = threadIdx.x;

    for (int i = tid; i < 768; i += 256) hg[i] = g_Hbuf[(t * BB + b) * HH + i];
    __syncthreads();

    int w = tid >> 5, lane = tid & 31;
    const float4* hg4 = (const float4*)hg;
#pragma unroll
    for (int i = 0; i < 2; i++) {
        int s = sc * 16 + w * 2 + i;
        const float4* e4 = (const float4*)(g_E + (b * SS + s) * HH);
        float d = 0.f;
#pragma unroll
        for (int c = 0; c < 6; c++) {
            float4 ev = e4[c * 32 + lane];
            float4 hv = hg4[c * 32 + lane];
            d += ev.x * hv.x + ev.y * hv.y + ev.z * hv.z + ev.w * hv.w;
        }
#pragma unroll
        for (int o = 16; o > 0; o >>= 1) d += __shfl_down_sync(0xffffffffu, d, o);
        if (lane == 0) g_sc[b * SS + s] = d + g_e0[b * SS + s];
    }
}

// ---------------- ctx: softmax (per block) + weighted sum, writes ctxT -------
// grid 128 = 32 b x 4 dim-chunks of 192; 192 threads, unroll 8.
__global__ void __launch_bounds__(192)
k_ctx(const float* __restrict__ enc, int t) {
    __shared__ float p[128];
    __shared__ float red[128];
    int b = blockIdx.x >> 2, hc = blockIdx.x & 3;
    int tid = threadIdx.x;

    if (tid < 128) {
        float v = g_sc[b * SS + tid];
        p[tid] = v;
        red[tid] = v;
    }
    __syncthreads();
    for (int o = 64; o > 0; o >>= 1) {
        if (tid < o) red[tid] = fmaxf(red[tid], red[tid + o]);
        __syncthreads();
    }
    float mx = red[0];
    __syncthreads();
    if (tid < 128) {
        float e = expf(p[tid] - mx);
        p[tid] = e;
        red[tid] = e;
    }
    __syncthreads();
    for (int o = 64; o > 0; o >>= 1) {
        if (tid < o) red[tid] += red[tid + o];
        __syncthreads();
    }
    float inv = 1.f / red[0];
    __syncthreads();
    if (tid < 128) p[tid] *= inv;
    __syncthreads();

    int dim = hc * 192 + tid;
    float acc = 0.f;
    const float* ep = enc + (b * SS) * HH + dim;
#pragma unroll 8
    for (int s = 0; s < SS; s++) acc += p[s] * ep[s * HH];
    g_ctxT[dim * 32 + b] = acc;
}

// ---------------- carry update: 256 blocks x 384 thr, j-tile 3 ---------------
// smem: w_s[3*1536] + red[12*32] = 19.5 KB
#define ATTH_SMEM ((3 * 1536 + 12 * 32) * 4)
__global__ void __launch_bounds__(384)
k_atth2(const float* __restrict__ Wctx, const float* __restrict__ bctx,
        int t) {
    extern __shared__ float sm[];
    float* w_s = sm;
    float* red = w_s + 3 * 1536;
    int tid = threadIdx.x;
    int j0 = blockIdx.x * 3;

    for (int i = tid; i < 1152; i += 384) {
        int row = i / 384, c4 = i % 384;
        *(float4*)(w_s + row * 1536 + c4 * 4) =
            *(const float4*)(Wctx + (j0 + row) * (2 * HH) + c4 * 4);
    }
    __syncthreads();

    int b = tid & 31, q = tid >> 5;          // q in 0..11
    int jl = q % 3, sub = q / 3;             // sub in 0..3
    float acc = 0.f;
#pragma unroll
    for (int ph = 0; ph < 2; ph++) {
        const float* ip = (ph ? g_hgT : g_ctxT) + sub * 192 * 32 + b;
        const float4* wp =
            (const float4*)(w_s + jl * 1536 + ph * 768 + sub * 192);
#pragma unroll 8
        for (int c = 0; c < 48; c++) {
            float4 v = wp[c];
            float h0 = ip[c * 128 + 0], h1 = ip[c * 128 + 32];
            float h2 = ip[c * 128 + 64], h3 = ip[c * 128 + 96];
            acc += h0 * v.x + h1 * v.y + h2 * v.z + h3 * v.w;
        }
    }
    red[q * 32 + b] = acc;
    __syncthreads();
    if (tid < 96) {
        int b2 = tid & 31, j2 = tid >> 5, j = j0 + j2;
        float s = 0.f;
#pragma unroll
        for (int qq = 0; qq < 4; qq++) s += red[(qq * 3 + j2) * 32 + b2];
        g_hT[j * 32 + b2] = tanhf(s + bctx[j]);
    }
}

// ---------------- bf16 split conversions ------------------------------------
__device__ __forceinline__ void split4(float4 v, __nv_bfloat16* hi,
                                       __nv_bfloat16* lo) {
    float f[4];
    f[0] = v.x; f[1] = v.y; f[2] = v.z; f[3] = v.w;
#pragma unroll
    for (int i = 0; i < 4; i++) {
        __nv_bfloat16 h = __float2bfloat16_rn(f[i]);
        hi[i] = h;
        lo[i] = __float2bfloat16_rn(f[i] - __bfloat162float(h));
    }
}

// B' = [Bh | Bl | Bh], rows padded to VPAD with zeros
__global__ void k_cvtB(const float* __restrict__ Wp) {
    long idx = (long)blockIdx.x * blockDim.x + threadIdx.x;
    if (idx >= (long)VPAD * 192) return;
    int row = (int)(idx / 192), c4 = (int)(idx % 192);
    float4 v = (row < VV) ? *(const float4*)(Wp + (long)row * HH + c4 * 4)
                          : make_float4(0.f, 0.f, 0.f, 0.f);
    __nv_bfloat16 hi[4], lo[4];
    split4(v, hi, lo);
    __nv_bfloat16* dst = g_Bs + (long)row * KS + c4 * 4;
    *(uint2*)(dst) = *(uint2*)hi;
    *(uint2*)(dst + HH) = *(uint2*)lo;
    *(uint2*)(dst + 2 * HH) = *(uint2*)hi;
}

// A' = [Ah | Ah | Al]
__global__ void k_cvtA() {
    int idx = blockIdx.x * blockDim.x + threadIdx.x;
    if (idx >= TT * BB * 192) return;
    int row = idx / 192, c4 = idx % 192;
    float4 v = *(const float4*)(g_Hbuf + row * HH + c4 * 4);
    __nv_bfloat16 hi[4], lo[4];
    split4(v, hi, lo);
    __nv_bfloat16* dst = g_As + row * KS + c4 * 4;
    *(uint2*)(dst) = *(uint2*)hi;
    *(uint2*)(dst + HH) = *(uint2*)hi;
    *(uint2*)(dst + 2 * HH) = *(uint2*)lo;
}

// ---------------- logits GEMM on tensor cores (mma.sync bf16) ----------------
#define LDP 40  // padded smem row length in bf16 (80 bytes)
__global__ void __launch_bounds__(256)
k_predmma(const float* __restrict__ bp, float* __restrict__ out) {
    __shared__ __nv_bfloat16 sA[2][128 * LDP];
    __shared__ __nv_bfloat16 sB[2][128 * LDP];

    int tid = threadIdx.x;
    int lane = tid & 31, wid = tid >> 5;
    int m0 = blockIdx.x * 128, n0 = blockIdx.y * 128;
    int warp_m = (wid >> 1) * 32;
    int warp_n = (wid & 1) * 64;

    const __nv_bfloat16* gA = g_As + (long)m0 * KS;
    const __nv_bfloat16* gB = g_Bs + (long)n0 * KS;

    float acc[2][8][4];
#pragma unroll
    for (int i = 0; i < 2; i++)
#pragma unroll
        for (int j = 0; j < 8; j++)
#pragma unroll
            for (int r = 0; r < 4; r++) acc[i][j][r] = 0.f;

    int ar0 = tid >> 2, ac0 = (tid & 3) * 8;
    int ar1 = (tid + 256) >> 2, ac1 = ((tid + 256) & 3) * 8;

    u32 sA0 = (u32)__cvta_generic_to_shared(&sA[0][0]);
    u32 sB0 = (u32)__cvta_generic_to_shared(&sB[0][0]);
    const u32 stageA = 128 * LDP * 2;
    const u32 stageB = 128 * LDP * 2;

    cp_async16(sA0 + (ar0 * LDP + ac0) * 2, gA + (long)ar0 * KS + ac0);
    cp_async16(sA0 + (ar1 * LDP + ac1) * 2, gA + (long)ar1 * KS + ac1);
    cp_async16(sB0 + (ar0 * LDP + ac0) * 2, gB + (long)ar0 * KS + ac0);
    cp_async16(sB0 + (ar1 * LDP + ac1) * 2, gB + (long)ar1 * KS + ac1);
    cp_commit();

    const int NIT = KS / 32;  // 72
    for (int it = 0; it < NIT; it++) {
        int buf = it & 1;
        if (it + 1 < NIT) {
            int k0 = (it + 1) * 32;
            u32 dA = sA0 + (buf ^ 1) * stageA;
            u32 dB = sB0 + (buf ^ 1) * stageB;
            cp_async16(dA + (ar0 * LDP + ac0) * 2, gA + (long)ar0 * KS + k0 + ac0);
            cp_async16(dA + (ar1 * LDP + ac1) * 2, gA + (long)ar1 * KS + k0 + ac1);
            cp_async16(dB + (ar0 * LDP + ac0) * 2, gB + (long)ar0 * KS + k0 + ac0);
            cp_async16(dB + (ar1 * LDP + ac1) * 2, gB + (long)ar1 * KS + k0 + ac1);
            cp_commit();
            cp_wait<1>();
        } else {
            cp_wait<0>();
        }
        __syncthreads();

        u32 baseA = sA0 + buf * stageA;
        u32 baseB = sB0 + buf * stageB;
#pragma unroll
        for (int ks = 0; ks < 2; ks++) {
            u32 areg[2][4];
#pragma unroll
            for (int mi = 0; mi < 2; mi++) {
                u32 addr = baseA +
                    ((warp_m + mi * 16 + (lane & 15)) * LDP +
                     ks * 16 + (lane >> 4) * 8) * 2;
                ldsm_x4(areg[mi][0], areg[mi][1], areg[mi][2], areg[mi][3],
                        addr);
            }
            u32 breg[4][4];
#pragma unroll
            for (int np = 0; np < 4; np++) {
                u32 addr = baseB +
                    ((warp_n + np * 16 + (lane & 15)) * LDP +
                     ks * 16 + (lane >> 4) * 8) * 2;
                ldsm_x4(breg[np][0], breg[np][1], breg[np][2], breg[np][3],
                        addr);
            }
#pragma unroll
            for (int mi = 0; mi < 2; mi++) {
#pragma unroll
                for (int nf = 0; nf < 8; nf++) {
                    int np = nf >> 1;
                    u32 b0 = (nf & 1) ? breg[np][1] : breg[np][0];
                    u32 b1 = (nf & 1) ? breg[np][3] : breg[np][2];
                    mma_bf16_16816(acc[mi][nf][0], acc[mi][nf][1],
                                   acc[mi][nf][2], acc[mi][nf][3],
                                   areg[mi][0], areg[mi][1], areg[mi][2],
                                   areg[mi][3], b0, b1);
                }
            }
        }
        __syncthreads();
    }

#pragma unroll
    for (int mi = 0; mi < 2; mi++) {
        int mA = m0 + warp_m + mi * 16 + (lane >> 2);
#pragma unroll
        for (int half = 0; half < 2; half++) {
            int m = mA + half * 8;
            int t = m >> 5, bb = m & 31;
            float* orow = out + (long)(bb * TT + t) * VV;
#pragma unroll
            for (int nf = 0; nf < 8; nf++) {
                int n = n0 + warp_n + nf * 8 + (lane & 3) * 2;
                if (n < VV) {
                    float2 bias = *(const float2*)(bp + n);
                    float2 v;
                    v.x = acc[mi][nf][half * 2 + 0] + bias.x;
                    v.y = acc[mi][nf][half * 2 + 1] + bias.y;
                    *(float2*)(orow + n) = v;
                }
            }
        }
    }
}

// ---------------- launcher ---------------------------------------------------
extern "C" void kernel_launch(void* const* d_in, const int* in_sizes, int n_in,
                              void* d_out, int out_size) {
    const float* x    = (const float*)d_in[0];
    const float* h0   = (const float*)d_in[1];
    const float* enc  = (const float*)d_in[2];
    const float* Wih  = (const float*)d_in[3];
    const float* Whh  = (const float*)d_in[4];
    const float* bih  = (const float*)d_in[5];
    const float* bhh  = (const float*)d_in[6];
    const float* Wp   = (const float*)d_in[7];
    const float* bp   = (const float*)d_in[8];
    const float* Watt = (const float*)d_in[9];
    const float* batt = (const float*)d_in[10];
    const float* Wctx = (const float*)d_in[11];
    const float* bctx = (const float*)d_in[12];
    float* out = (float*)d_out;

    cudaFuncSetAttribute(k_gru2, cudaFuncAttributeMaxDynamicSharedMemorySize,
                         GRU_SMEM);
    cudaFuncSetAttribute(k_atth2, cudaFuncAttributeMaxDynamicSharedMemorySize,
                         ATTH_SMEM);

    k_prolog<<<PROLOG_BLOCKS, 256>>>(x, Wih, bih, enc, Watt, batt, h0);
    k_cvtB<<<(VPAD * 192 + 255) / 256, 256>>>(Wp);

    for (int t = 0; t < TT; t++) {
        k_gru2<<<256, 384, GRU_SMEM>>>(Whh, bhh, t);
        k_score<<<BB * 8, 256>>>(t);
        k_ctx<<<BB * 4, 192>>>(enc, t);
        k_atth2<<<256, 384, ATTH_SMEM>>>(Wctx, bctx, t);
    }

    k_cvtA<<<(TT * BB * 192 + 255) / 256, 256>>>();
    k_predmma<<<dim3((TT * BB) / 128, VPAD / 128), 256>>>(bp, out);
}

// round 16
// speedup vs baseline: 1.6811x; 1.0378x over previous
#include <cuda_runtime.h>
#include <cuda_bf16.h>
#include <cstdint>
#include <math.h>

typedef unsigned int u32;

#define BB 32
#define TT 48
#define DD 768
#define HH 768
#define SS 128
#define VV 28996
#define H3 2304
#define VPAD 29056           // 227 * 128
#define KS 2304              // split-K: [hi | hi/lo | lo/hi]

// ---------------- scratch (static device globals; no allocation) -------------
__device__ float g_GI[TT * BB * H3];
__device__ float g_Hbuf[TT * BB * HH];
__device__ float g_hT[HH * BB];                // carry h, TRANSPOSED [k][b]
__device__ float g_hgT[HH * BB];               // current-step GRU out, transposed
__device__ float g_ctxT[HH * BB];              // attention ctx, transposed
__device__ float g_E[BB * SS * HH];
__device__ float g_e0[BB * SS];
__device__ float g_sc[BB * SS];                // raw attention scores
__device__ __nv_bfloat16 g_As[TT * BB * KS];   // A' = [Ah | Ah | Al]
__device__ __nv_bfloat16 g_Bs[VPAD * KS];      // B' = [Bh | Bl | Bh]

// ---------------- PTX helpers (lvalue-safe wrappers) -------------------------
__device__ __forceinline__ void ldsm_x4(u32& r0, u32& r1, u32& r2, u32& r3,
                                        u32 addr) {
    asm volatile(
        "ldmatrix.sync.aligned.m8n8.x4.shared.b16 {%0,%1,%2,%3}, [%4];"
        : "=r"(r0), "=r"(r1), "=r"(r2), "=r"(r3)
        : "r"(addr));
}

__device__ __forceinline__ void mma_bf16_16816(float& c0, float& c1,
                                               float& c2, float& c3,
                                               u32 a0, u32 a1, u32 a2, u32 a3,
                                               u32 b0, u32 b1) {
    asm volatile(
        "mma.sync.aligned.m16n8k16.row.col.f32.bf16.bf16.f32 "
        "{%0,%1,%2,%3}, {%4,%5,%6,%7}, {%8,%9}, {%0,%1,%2,%3};"
        : "+f"(c0), "+f"(c1), "+f"(c2), "+f"(c3)
        : "r"(a0), "r"(a1), "r"(a2), "r"(a3), "r"(b0), "r"(b1));
}

__device__ __forceinline__ void cp_async16(u32 dst, const void* src) {
    asm volatile("cp.async.cg.shared.global [%0], [%1], 16;\n" ::"r"(dst),
                 "l"(src));
}

__device__ __forceinline__ void cp_commit() {
    asm volatile("cp.async.commit_group;\n");
}

template <int N>
__device__ __forceinline__ void cp_wait() {
    asm volatile("cp.async.wait_group %0;\n" ::"n"(N));
}

// ---------------- fused prologue ---------------------------------------------
// blocks [0,96): init_hT | [96,960): GI gemm | [960,1728): E gemm | rest: e0
#define PROLOG_BLOCKS 1856
__global__ void __launch_bounds__(256)
k_prolog(const float* __restrict__ x, const float* __restrict__ Wih,
         const float* __restrict__ bih, const float* __restrict__ enc,
         const float* __restrict__ Watt, const float* __restrict__ batt,
         const float* __restrict__ hs) {
    __shared__ float as[16][68];
    __shared__ float bs[16][68];
    int bid = blockIdx.x;
    int tid = threadIdx.x;

    if (bid < 96) {
        int i = bid * 256 + tid;
        int b = i / HH, j = i % HH;
        g_hT[j * BB + b] = hs[i];
        return;
    }
    if (bid < 960) {
        int id = bid - 96;
        int n0 = (id % 36) * 64, m0 = (id / 36) * 64;
        int tx = tid & 15, ty = tid >> 4;
        int lm = tid >> 2, lk = (tid & 3) * 4;

        int gm = m0 + lm;
        const float* aptr = x + ((gm & 31) * TT + (gm >> 5)) * DD;
        const float* bptr = Wih + (n0 + lm) * DD;

        float acc[4][4];
#pragma unroll
        for (int i = 0; i < 4; i++)
#pragma unroll
            for (int j = 0; j < 4; j++) acc[i][j] = 0.f;

        for (int k0 = 0; k0 < DD; k0 += 16) {
            float4 av = *(const float4*)(aptr + k0 + lk);
            float4 bv = *(const float4*)(bptr + k0 + lk);
            as[lk + 0][lm] = av.x; as[lk + 1][lm] = av.y;
            as[lk + 2][lm] = av.z; as[lk + 3][lm] = av.w;
            bs[lk + 0][lm] = bv.x; bs[lk + 1][lm] = bv.y;
            bs[lk + 2][lm] = bv.z; bs[lk + 3][lm] = bv.w;
            __syncthreads();
#pragma unroll
            for (int kk = 0; kk < 16; kk++) {
                float4 a4 = *(const float4*)&as[kk][ty * 4];
                float4 b4 = *(const float4*)&bs[kk][tx * 4];
                acc[0][0] += a4.x * b4.x; acc[0][1] += a4.x * b4.y;
                acc[0][2] += a4.x * b4.z; acc[0][3] += a4.x * b4.w;
                acc[1][0] += a4.y * b4.x; acc[1][1] += a4.y * b4.y;
                acc[1][2] += a4.y * b4.z; acc[1][3] += a4.y * b4.w;
                acc[2][0] += a4.z * b4.x; acc[2][1] += a4.z * b4.y;
                acc[2][2] += a4.z * b4.z; acc[2][3] += a4.z * b4.w;
                acc[3][0] += a4.w * b4.x; acc[3][1] += a4.w * b4.y;
                acc[3][2] += a4.w * b4.z; acc[3][3] += a4.w * b4.w;
            }
            __syncthreads();
        }
#pragma unroll
        for (int i = 0; i < 4; i++) {
            int m = m0 + ty * 4 + i;
#pragma unroll
            for (int j = 0; j < 4; j++) {
                int n = n0 + tx * 4 + j;
                g_GI[m * H3 + n] = acc[i][j] + bih[n];
            }
        }
        return;
    }
    if (bid < 1728) {
        int id = bid - 960;
        int n0 = (id % 12) * 64, m0 = (id / 12) * 64;
        int tx = tid & 15, ty = tid >> 4;
        int lm = tid >> 2, lk = (tid & 3) * 4;
        int lr = tid >> 4, lc = (tid & 15) * 4;

        const float* aptr = enc + (m0 + lm) * HH;

        float acc[4][4];
#pragma unroll
        for (int i = 0; i < 4; i++)
#pragma unroll
            for (int j = 0; j < 4; j++) acc[i][j] = 0.f;

        for (int k0 = 0; k0 < HH; k0 += 16) {
            float4 av = *(const float4*)(aptr + k0 + lk);
            float4 bv = *(const float4*)(Watt + (k0 + lr) * HH + n0 + lc);
            as[lk + 0][lm] = av.x; as[lk + 1][lm] = av.y;
            as[lk + 2][lm] = av.z; as[lk + 3][lm] = av.w;
            *(float4*)&bs[lr][lc] = bv;
            __syncthreads();
#pragma unroll
            for (int kk = 0; kk < 16; kk++) {
                float4 a4 = *(const float4*)&as[kk][ty * 4];
                float4 b4 = *(const float4*)&bs[kk][tx * 4];
                acc[0][0] += a4.x * b4.x; acc[0][1] += a4.x * b4.y;
                acc[0][2] += a4.x * b4.z; acc[0][3] += a4.x * b4.w;
                acc[1][0] += a4.y * b4.x; acc[1][1] += a4.y * b4.y;
                acc[1][2] += a4.y * b4.z; acc[1][3] += a4.y * b4.w;
                acc[2][0] += a4.z * b4.x; acc[2][1] += a4.z * b4.y;
                acc[2][2] += a4.z * b4.z; acc[2][3] += a4.z * b4.w;
                acc[3][0] += a4.w * b4.x; acc[3][1] += a4.w * b4.y;
                acc[3][2] += a4.w * b4.z; acc[3][3] += a4.w * b4.w;
            }
            __syncthreads();
        }
#pragma unroll
        for (int i = 0; i < 4; i++) {
            int m = m0 + ty * 4 + i;
#pragma unroll
            for (int j = 0; j < 4; j++) {
                g_E[m * HH + n0 + tx * 4 + j] = acc[i][j];
            }
        }
        return;
    }
    {
        int id = bid - 1728;
        int gw = id * 8 + (tid >> 5);
        int lane = tid & 31;
        for (int r = gw; r < BB * SS; r += 1024) {
            const float4* e4 = (const float4*)(enc + r * HH);
            const float4* b4 = (const float4*)batt;
            float s = 0.f;
#pragma unroll
            for (int c = 0; c < 6; c++) {
                float4 ev = e4[c * 32 + lane];
                float4 bv = b4[c * 32 + lane];
                s += ev.x * bv.x + ev.y * bv.y + ev.z * bv.z + ev.w * bv.w;
            }
#pragma unroll
            for (int o = 16; o > 0; o >>= 1)
                s += __shfl_down_sync(0xffffffffu, s, o);
            if (lane == 0) g_e0[r] = s;
        }
    }
}

// ---------------- GRU step: 256 blocks x 384 thr, j-tile 3 -------------------
#define GRU_SMEM ((9 * 768 + 3 * 12 * 32) * 4)
__global__ void __launch_bounds__(384)
k_gru2(const float* __restrict__ Whh, const float* __restrict__ bhh, int t) {
    extern __shared__ float sm[];
    float* w_s = sm;
    float* red = w_s + 9 * 768;
    int tid = threadIdx.x;
    int j0 = blockIdx.x * 3;

    for (int i = tid; i < 1728; i += 384) {
        int row = i / 192, c4 = i % 192;
        int g = row / 3, jl = row % 3;
        *(float4*)(w_s + row * 768 + c4 * 4) =
            *(const float4*)(Whh + (g * HH + j0 + jl) * HH + c4 * 4);
    }
    __syncthreads();

    int b = tid & 31, q = tid >> 5;
    int jl = q % 3, qt = q / 3;
    int kbeg = qt * 192;
    const float4* w0 = (const float4*)(w_s + (0 + jl) * 768 + kbeg);
    const float4* w1 = (const float4*)(w_s + (3 + jl) * 768 + kbeg);
    const float4* w2 = (const float4*)(w_s + (6 + jl) * 768 + kbeg);
    const float* hp = g_hT + kbeg * 32 + b;
    float a0 = 0.f, a1 = 0.f, a2 = 0.f;
#pragma unroll 8
    for (int c = 0; c < 48; c++) {
        float4 v0 = w0[c], v1 = w1[c], v2 = w2[c];
        float h0 = hp[c * 128 + 0], h1 = hp[c * 128 + 32];
        float h2 = hp[c * 128 + 64], h3 = hp[c * 128 + 96];
        a0 += h0 * v0.x + h1 * v0.y + h2 * v0.z + h3 * v0.w;
        a1 += h0 * v1.x + h1 * v1.y + h2 * v1.z + h3 * v1.w;
        a2 += h0 * v2.x + h1 * v2.y + h2 * v2.z + h3 * v2.w;
    }
    red[(0 * 12 + q) * 32 + b] = a0;
    red[(1 * 12 + q) * 32 + b] = a1;
    red[(2 * 12 + q) * 32 + b] = a2;
    __syncthreads();

    if (tid < 96) {
        int b2 = tid & 31, j2 = tid >> 5, j = j0 + j2;
        float ar = 0.f, az = 0.f, an = 0.f;
#pragma unroll
        for (int qq = 0; qq < 4; qq++) {
            int q2 = qq * 3 + j2;
            ar += red[(0 * 12 + q2) * 32 + b2];
            az += red[(1 * 12 + q2) * 32 + b2];
            an += red[(2 * 12 + q2) * 32 + b2];
        }
        const float* gi = g_GI + (t * BB + b2) * H3;
        float r = 1.f / (1.f + expf(-(gi[j] + ar + bhh[j])));
        float z = 1.f / (1.f + expf(-(gi[HH + j] + az + bhh[HH + j])));
        float n = tanhf(gi[2 * HH + j] + r * (an + bhh[2 * HH + j]));
        float hprev = g_hT[j * 32 + b2];
        float hnew = (1.f - z) * n + z * hprev;
        g_Hbuf[(t * BB + b2) * HH + j] = hnew;
        g_hgT[j * 32 + b2] = hnew;
    }
}

// ---------------- scores: g_sc[b][s] = h . E[b,s] + e0  (256 blocks) ---------
__global__ void __launch_bounds__(256)
k_score(int t) {
    __shared__ __align__(16) float hg[768];
    int b = blockIdx.x >> 3, sc = blockIdx.x & 7;
    int tid = threadIdx.x;

    for (int i = tid; i < 768; i += 256) hg[i] = g_Hbuf[(t * BB + b) * HH + i];
    __syncthreads();

    int w = tid >> 5, lane = tid & 31;
    const float4* hg4 = (const float4*)hg;
#pragma unroll
    for (int i = 0; i < 2; i++) {
        int s = sc * 16 + w * 2 + i;
        const float4* e4 = (const float4*)(g_E + (b * SS + s) * HH);
        float d = 0.f;
#pragma unroll
        for (int c = 0; c < 6; c++) {
            float4 ev = e4[c * 32 + lane];
            float4 hv = hg4[c * 32 + lane];
            d += ev.x * hv.x + ev.y * hv.y + ev.z * hv.z + ev.w * hv.w;
        }
#pragma unroll
        for (int o = 16; o > 0; o >>= 1) d += __shfl_down_sync(0xffffffffu, d, o);
        if (lane == 0) g_sc[b * SS + s] = d + g_e0[b * SS + s];
    }
}

// ---------------- ctx: softmax (per block) + weighted sum, writes ctxT -------
__global__ void __launch_bounds__(192)
k_ctx(const float* __restrict__ enc, int t) {
    __shared__ float p[128];
    __shared__ float red[128];
    int b = blockIdx.x >> 2, hc = blockIdx.x & 3;
    int tid = threadIdx.x;

    if (tid < 128) {
        float v = g_sc[b * SS + tid];
        p[tid] = v;
        red[tid] = v;
    }
    __syncthreads();
    for (int o = 64; o > 0; o >>= 1) {
        if (tid < o) red[tid] = fmaxf(red[tid], red[tid + o]);
        __syncthreads();
    }
    float mx = red[0];
    __syncthreads();
    if (tid < 128) {
        float e = expf(p[tid] - mx);
        p[tid] = e;
        red[tid] = e;
    }
    __syncthreads();
    for (int o = 64; o > 0; o >>= 1) {
        if (tid < o) red[tid] += red[tid + o];
        __syncthreads();
    }
    float inv = 1.f / red[0];
    __syncthreads();
    if (tid < 128) p[tid] *= inv;
    __syncthreads();

    int dim = hc * 192 + tid;
    float acc = 0.f;
    const float* ep = enc + (b * SS) * HH + dim;
#pragma unroll 8
    for (int s = 0; s < SS; s++) acc += p[s] * ep[s * HH];
    g_ctxT[dim * 32 + b] = acc;
}

// ---------------- carry update: 256 blocks x 384 thr, j-tile 3 ---------------
#define ATTH_SMEM ((3 * 1536 + 12 * 32) * 4)
__global__ void __launch_bounds__(384)
k_atth2(const float* __restrict__ Wctx, const float* __restrict__ bctx,
        int t) {
    extern __shared__ float sm[];
    float* w_s = sm;
    float* red = w_s + 3 * 1536;
    int tid = threadIdx.x;
    int j0 = blockIdx.x * 3;

    for (int i = tid; i < 1152; i += 384) {
        int row = i / 384, c4 = i % 384;
        *(float4*)(w_s + row * 1536 + c4 * 4) =
            *(const float4*)(Wctx + (j0 + row) * (2 * HH) + c4 * 4);
    }
    __syncthreads();

    int b = tid & 31, q = tid >> 5;
    int jl = q % 3, sub = q / 3;
    float acc = 0.f;
#pragma unroll
    for (int ph = 0; ph < 2; ph++) {
        const float* ip = (ph ? g_hgT : g_ctxT) + sub * 192 * 32 + b;
        const float4* wp =
            (const float4*)(w_s + jl * 1536 + ph * 768 + sub * 192);
#pragma unroll 8
        for (int c = 0; c < 48; c++) {
            float4 v = wp[c];
            float h0 = ip[c * 128 + 0], h1 = ip[c * 128 + 32];
            float h2 = ip[c * 128 + 64], h3 = ip[c * 128 + 96];
            acc += h0 * v.x + h1 * v.y + h2 * v.z + h3 * v.w;
        }
    }
    red[q * 32 + b] = acc;
    __syncthreads();
    if (tid < 96) {
        int b2 = tid & 31, j2 = tid >> 5, j = j0 + j2;
        float s = 0.f;
#pragma unroll
        for (int qq = 0; qq < 4; qq++) s += red[(qq * 3 + j2) * 32 + b2];
        g_hT[j * 32 + b2] = tanhf(s + bctx[j]);
    }
}

// ---------------- bf16 split conversions ------------------------------------
__device__ __forceinline__ void split4(float4 v, __nv_bfloat16* hi,
                                       __nv_bfloat16* lo) {
    float f[4];
    f[0] = v.x; f[1] = v.y; f[2] = v.z; f[3] = v.w;
#pragma unroll
    for (int i = 0; i < 4; i++) {
        __nv_bfloat16 h = __float2bfloat16_rn(f[i]);
        hi[i] = h;
        lo[i] = __float2bfloat16_rn(f[i] - __bfloat162float(h));
    }
}

// B' = [Bh | Bl | Bh], rows padded to VPAD with zeros
__global__ void k_cvtB(const float* __restrict__ Wp) {
    long idx = (long)blockIdx.x * blockDim.x + threadIdx.x;
    if (idx >= (long)VPAD * 192) return;
    int row = (int)(idx / 192), c4 = (int)(idx % 192);
    float4 v = (row < VV) ? *(const float4*)(Wp + (long)row * HH + c4 * 4)
                          : make_float4(0.f, 0.f, 0.f, 0.f);
    __nv_bfloat16 hi[4], lo[4];
    split4(v, hi, lo);
    __nv_bfloat16* dst = g_Bs + (long)row * KS + c4 * 4;
    *(uint2*)(dst) = *(uint2*)hi;
    *(uint2*)(dst + HH) = *(uint2*)lo;
    *(uint2*)(dst + 2 * HH) = *(uint2*)hi;
}

// A' = [Ah | Ah | Al]
__global__ void k_cvtA() {
    int idx = blockIdx.x * blockDim.x + threadIdx.x;
    if (idx >= TT * BB * 192) return;
    int row = idx / 192, c4 = idx % 192;
    float4 v = *(const float4*)(g_Hbuf + row * HH + c4 * 4);
    __nv_bfloat16 hi[4], lo[4];
    split4(v, hi, lo);
    __nv_bfloat16* dst = g_As + row * KS + c4 * 4;
    *(uint2*)(dst) = *(uint2*)hi;
    *(uint2*)(dst + HH) = *(uint2*)hi;
    *(uint2*)(dst + 2 * HH) = *(uint2*)lo;
}

// ---------------- logits GEMM on tensor cores (mma.sync bf16) ----------------
// K slab 64 (NIT=36, half the syncs of the 32-slab version). Rows padded to
// 72 bf16 (144 B) -> 8-row ldmatrix groups hit distinct bank groups.
#define LDP2 72
#define PSTG (128 * LDP2)                 // bf16 elems per stage per array
#define PRED_SMEM (4 * PSTG * 2)          // 73728 B dynamic smem
__global__ void __launch_bounds__(256)
k_predmma(const float* __restrict__ bp, float* __restrict__ out) {
    extern __shared__ __nv_bfloat16 smp[];
    __nv_bfloat16* sA = smp;              // [2][PSTG]
    __nv_bfloat16* sB = smp + 2 * PSTG;   // [2][PSTG]

    int tid = threadIdx.x;
    int lane = tid & 31, wid = tid >> 5;
    int m0 = blockIdx.x * 128, n0 = blockIdx.y * 128;
    int warp_m = (wid >> 1) * 32;
    int warp_n = (wid & 1) * 64;

    const __nv_bfloat16* gA = g_As + (long)m0 * KS;
    const __nv_bfloat16* gB = g_Bs + (long)n0 * KS;

    float acc[2][8][4];
#pragma unroll
    for (int i = 0; i < 2; i++)
#pragma unroll
        for (int j = 0; j < 8; j++)
#pragma unroll
            for (int r = 0; r < 4; r++) acc[i][j][r] = 0.f;

    // copy map: 128 rows x 64 cols = 1024 chunks of 8 per array; 4/thread
    int cr[4], cc[4];
#pragma unroll
    for (int j = 0; j < 4; j++) {
        int c = tid + j * 256;
        cr[j] = c >> 3;
        cc[j] = (c & 7) * 8;
    }

    u32 sA0 = (u32)__cvta_generic_to_shared(sA);
    u32 sB0 = (u32)__cvta_generic_to_shared(sB);
    const u32 stage = PSTG * 2;  // bytes

    // prologue: stage 0 (k0 = 0)
#pragma unroll
    for (int j = 0; j < 4; j++) {
        cp_async16(sA0 + (cr[j] * LDP2 + cc[j]) * 2, gA + (long)cr[j] * KS + cc[j]);
        cp_async16(sB0 + (cr[j] * LDP2 + cc[j]) * 2, gB + (long)cr[j] * KS + cc[j]);
    }
    cp_commit();

    const int NIT = KS / 64;  // 36
    for (int it = 0; it < NIT; it++) {
        int buf = it & 1;
        if (it + 1 < NIT) {
            int k0 = (it + 1) * 64;
            u32 dA = sA0 + (buf ^ 1) * stage;
            u32 dB = sB0 + (buf ^ 1) * stage;
#pragma unroll
            for (int j = 0; j < 4; j++) {
                cp_async16(dA + (cr[j] * LDP2 + cc[j]) * 2,
                           gA + (long)cr[j] * KS + k0 + cc[j]);
                cp_async16(dB + (cr[j] * LDP2 + cc[j]) * 2,
                           gB + (long)cr[j] * KS + k0 + cc[j]);
            }
            cp_commit();
            cp_wait<1>();
        } else {
            cp_wait<0>();
        }
        __syncthreads();

        u32 baseA = sA0 + buf * stage;
        u32 baseB = sB0 + buf * stage;
#pragma unroll
        for (int ks = 0; ks < 4; ks++) {
            u32 areg[2][4];
#pragma unroll
            for (int mi = 0; mi < 2; mi++) {
                u32 addr = baseA +
                    ((warp_m + mi * 16 + (lane & 15)) * LDP2 +
                     ks * 16 + (lane >> 4) * 8) * 2;
                ldsm_x4(areg[mi][0], areg[mi][1], areg[mi][2], areg[mi][3],
                        addr);
            }
            u32 breg[4][4];
#pragma unroll
            for (int np = 0; np < 4; np++) {
                u32 addr = baseB +
                    ((warp_n + np * 16 + (lane & 15)) * LDP2 +
                     ks * 16 + (lane >> 4) * 8) * 2;
                ldsm_x4(breg[np][0], breg[np][1], breg[np][2], breg[np][3],
                        addr);
            }
#pragma unroll
            for (int mi = 0; mi < 2; mi++) {
#pragma unroll
                for (int nf = 0; nf < 8; nf++) {
                    int np = nf >> 1;
                    u32 b0 = (nf & 1) ? breg[np][1] : breg[np][0];
                    u32 b1 = (nf & 1) ? breg[np][3] : breg[np][2];
                    mma_bf16_16816(acc[mi][nf][0], acc[mi][nf][1],
                                   acc[mi][nf][2], acc[mi][nf][3],
                                   areg[mi][0], areg[mi][1], areg[mi][2],
                                   areg[mi][3], b0, b1);
                }
            }
        }
        __syncthreads();
    }

#pragma unroll
    for (int mi = 0; mi < 2; mi++) {
        int mA = m0 + warp_m + mi * 16 + (lane >> 2);
#pragma unroll
        for (int half = 0; half < 2; half++) {
            int m = mA + half * 8;
            int t = m >> 5, bb = m & 31;
            float* orow = out + (long)(bb * TT + t) * VV;
#pragma unroll
            for (int nf = 0; nf < 8; nf++) {
                int n = n0 + warp_n + nf * 8 + (lane & 3) * 2;
                if (n < VV) {
                    float2 bias = *(const float2*)(bp + n);
                    float2 v;
                    v.x = acc[mi][nf][half * 2 + 0] + bias.x;
                    v.y = acc[mi][nf][half * 2 + 1] + bias.y;
                    *(float2*)(orow + n) = v;
                }
            }
        }
    }
}

// ---------------- launcher ---------------------------------------------------
extern "C" void kernel_launch(void* const* d_in, const int* in_sizes, int n_in,
                              void* d_out, int out_size) {
    const float* x    = (const float*)d_in[0];
    const float* h0   = (const float*)d_in[1];
    const float* enc  = (const float*)d_in[2];
    const float* Wih  = (const float*)d_in[3];
    const float* Whh  = (const float*)d_in[4];
    const float* bih  = (const float*)d_in[5];
    const float* bhh  = (const float*)d_in[6];
    const float* Wp   = (const float*)d_in[7];
    const float* bp   = (const float*)d_in[8];
    const float* Watt = (const float*)d_in[9];
    const float* batt = (const float*)d_in[10];
    const float* Wctx = (const float*)d_in[11];
    const float* bctx = (const float*)d_in[12];
    float* out = (float*)d_out;

    cudaFuncSetAttribute(k_gru2, cudaFuncAttributeMaxDynamicSharedMemorySize,
                         GRU_SMEM);
    cudaFuncSetAttribute(k_atth2, cudaFuncAttributeMaxDynamicSharedMemorySize,
                         ATTH_SMEM);
    cudaFuncSetAttribute(k_predmma, cudaFuncAttributeMaxDynamicSharedMemorySize,
                         PRED_SMEM);

    k_prolog<<<PROLOG_BLOCKS, 256>>>(x, Wih, bih, enc, Watt, batt, h0);
    k_cvtB<<<(VPAD * 192 + 255) / 256, 256>>>(Wp);

    for (int t = 0; t < TT; t++) {
        k_gru2<<<256, 384, GRU_SMEM>>>(Whh, bhh, t);
        k_score<<<BB * 8, 256>>>(t);
        k_ctx<<<BB * 4, 192>>>(enc, t);
        k_atth2<<<256, 384, ATTH_SMEM>>>(Wctx, bctx, t);
    }

    k_cvtA<<<(TT * BB * 192 + 255) / 256, 256>>>();
    k_predmma<<<dim3((TT * BB) / 128, VPAD / 128), 256, PRED_SMEM>>>(bp, out);
}

// round 17
// speedup vs baseline: 1.6964x; 1.0091x over previous
#include <cuda_runtime.h>
#include <cuda_bf16.h>
#include <cstdint>
#include <math.h>

typedef unsigned int u32;

#define BB 32
#define TT 48
#define DD 768
#define HH 768
#define SS 128
#define VV 28996
#define H3 2304
#define VPAD 29056           // 227 * 128
#define KS 2304              // split-K: [hi | hi/lo | lo/hi]

// ---------------- scratch (static device globals; no allocation) -------------
__device__ float g_GI[TT * BB * H3];
__device__ float g_Hbuf[TT * BB * HH];
__device__ float g_hT[HH * BB];                // carry h, TRANSPOSED [k][b]
__device__ float g_hgT[HH * BB];               // current-step GRU out, transposed
__device__ float g_ctxT[HH * BB];              // attention ctx, transposed
__device__ float g_E[BB * SS * HH];
__device__ float g_e0[BB * SS];
__device__ __nv_bfloat16 g_As[TT * BB * KS];   // A' = [Ah | Ah | Al]
__device__ __nv_bfloat16 g_Bs[VPAD * KS];      // B' = [Bh | Bl | Bh]

// ---------------- PTX helpers (lvalue-safe wrappers) -------------------------
__device__ __forceinline__ void ldsm_x4(u32& r0, u32& r1, u32& r2, u32& r3,
                                        u32 addr) {
    asm volatile(
        "ldmatrix.sync.aligned.m8n8.x4.shared.b16 {%0,%1,%2,%3}, [%4];"
        : "=r"(r0), "=r"(r1), "=r"(r2), "=r"(r3)
        : "r"(addr));
}

__device__ __forceinline__ void mma_bf16_16816(float& c0, float& c1,
                                               float& c2, float& c3,
                                               u32 a0, u32 a1, u32 a2, u32 a3,
                                               u32 b0, u32 b1) {
    asm volatile(
        "mma.sync.aligned.m16n8k16.row.col.f32.bf16.bf16.f32 "
        "{%0,%1,%2,%3}, {%4,%5,%6,%7}, {%8,%9}, {%0,%1,%2,%3};"
        : "+f"(c0), "+f"(c1), "+f"(c2), "+f"(c3)
        : "r"(a0), "r"(a1), "r"(a2), "r"(a3), "r"(b0), "r"(b1));
}

__device__ __forceinline__ void cp_async16(u32 dst, const void* src) {
    asm volatile("cp.async.cg.shared.global [%0], [%1], 16;\n" ::"r"(dst),
                 "l"(src));
}

__device__ __forceinline__ void cp_commit() {
    asm volatile("cp.async.commit_group;\n");
}

template <int N>
__device__ __forceinline__ void cp_wait() {
    asm volatile("cp.async.wait_group %0;\n" ::"n"(N));
}

__device__ __forceinline__ u32 smem_addr_u32(const void* p) {
    return (u32)__cvta_generic_to_shared(p);
}

__device__ __forceinline__ float dsmem_ld_f32(u32 local_addr, u32 rank) {
    u32 raddr;
    asm volatile("mapa.shared::cluster.u32 %0, %1, %2;"
                 : "=r"(raddr)
                 : "r"(local_addr), "r"(rank));
    float v;
    asm volatile("ld.shared::cluster.f32 %0, [%1];" : "=f"(v) : "r"(raddr));
    return v;
}

__device__ __forceinline__ void cluster_sync_aligned() {
    asm volatile("barrier.cluster.arrive.aligned;" ::: "memory");
    asm volatile("barrier.cluster.wait.aligned;" ::: "memory");
}

// ---------------- fused prologue ---------------------------------------------
// blocks [0,96): init_hT | [96,960): GI gemm | [960,1728): E gemm | rest: e0
#define PROLOG_BLOCKS 1856
__global__ void __launch_bounds__(256)
k_prolog(const float* __restrict__ x, const float* __restrict__ Wih,
         const float* __restrict__ bih, const float* __restrict__ enc,
         const float* __restrict__ Watt, const float* __restrict__ batt,
         const float* __restrict__ hs) {
    __shared__ float as[16][68];
    __shared__ float bs[16][68];
    int bid = blockIdx.x;
    int tid = threadIdx.x;

    if (bid < 96) {
        int i = bid * 256 + tid;
        int b = i / HH, j = i % HH;
        g_hT[j * BB + b] = hs[i];
        return;
    }
    if (bid < 960) {
        int id = bid - 96;
        int n0 = (id % 36) * 64, m0 = (id / 36) * 64;
        int tx = tid & 15, ty = tid >> 4;
        int lm = tid >> 2, lk = (tid & 3) * 4;

        int gm = m0 + lm;
        const float* aptr = x + ((gm & 31) * TT + (gm >> 5)) * DD;
        const float* bptr = Wih + (n0 + lm) * DD;

        float acc[4][4];
#pragma unroll
        for (int i = 0; i < 4; i++)
#pragma unroll
            for (int j = 0; j < 4; j++) acc[i][j] = 0.f;

        for (int k0 = 0; k0 < DD; k0 += 16) {
            float4 av = *(const float4*)(aptr + k0 + lk);
            float4 bv = *(const float4*)(bptr + k0 + lk);
            as[lk + 0][lm] = av.x; as[lk + 1][lm] = av.y;
            as[lk + 2][lm] = av.z; as[lk + 3][lm] = av.w;
            bs[lk + 0][lm] = bv.x; bs[lk + 1][lm] = bv.y;
            bs[lk + 2][lm] = bv.z; bs[lk + 3][lm] = bv.w;
            __syncthreads();
#pragma unroll
            for (int kk = 0; kk < 16; kk++) {
                float4 a4 = *(const float4*)&as[kk][ty * 4];
                float4 b4 = *(const float4*)&bs[kk][tx * 4];
                acc[0][0] += a4.x * b4.x; acc[0][1] += a4.x * b4.y;
                acc[0][2] += a4.x * b4.z; acc[0][3] += a4.x * b4.w;
                acc[1][0] += a4.y * b4.x; acc[1][1] += a4.y * b4.y;
                acc[1][2] += a4.y * b4.z; acc[1][3] += a4.y * b4.w;
                acc[2][0] += a4.z * b4.x; acc[2][1] += a4.z * b4.y;
                acc[2][2] += a4.z * b4.z; acc[2][3] += a4.z * b4.w;
                acc[3][0] += a4.w * b4.x; acc[3][1] += a4.w * b4.y;
                acc[3][2] += a4.w * b4.z; acc[3][3] += a4.w * b4.w;
            }
            __syncthreads();
        }
#pragma unroll
        for (int i = 0; i < 4; i++) {
            int m = m0 + ty * 4 + i;
#pragma unroll
            for (int j = 0; j < 4; j++) {
                int n = n0 + tx * 4 + j;
                g_GI[m * H3 + n] = acc[i][j] + bih[n];
            }
        }
        return;
    }
    if (bid < 1728) {
        int id = bid - 960;
        int n0 = (id % 12) * 64, m0 = (id / 12) * 64;
        int tx = tid & 15, ty = tid >> 4;
        int lm = tid >> 2, lk = (tid & 3) * 4;
        int lr = tid >> 4, lc = (tid & 15) * 4;

        const float* aptr = enc + (m0 + lm) * HH;

        float acc[4][4];
#pragma unroll
        for (int i = 0; i < 4; i++)
#pragma unroll
            for (int j = 0; j < 4; j++) acc[i][j] = 0.f;

        for (int k0 = 0; k0 < HH; k0 += 16) {
            float4 av = *(const float4*)(aptr + k0 + lk);
            float4 bv = *(const float4*)(Watt + (k0 + lr) * HH + n0 + lc);
            as[lk + 0][lm] = av.x; as[lk + 1][lm] = av.y;
            as[lk + 2][lm] = av.z; as[lk + 3][lm] = av.w;
            *(float4*)&bs[lr][lc] = bv;
            __syncthreads();
#pragma unroll
            for (int kk = 0; kk < 16; kk++) {
                float4 a4 = *(const float4*)&as[kk][ty * 4];
                float4 b4 = *(const float4*)&bs[kk][tx * 4];
                acc[0][0] += a4.x * b4.x; acc[0][1] += a4.x * b4.y;
                acc[0][2] += a4.x * b4.z; acc[0][3] += a4.x * b4.w;
                acc[1][0] += a4.y * b4.x; acc[1][1] += a4.y * b4.y;
                acc[1][2] += a4.y * b4.z; acc[1][3] += a4.y * b4.w;
                acc[2][0] += a4.z * b4.x; acc[2][1] += a4.z * b4.y;
                acc[2][2] += a4.z * b4.z; acc[2][3] += a4.z * b4.w;
                acc[3][0] += a4.w * b4.x; acc[3][1] += a4.w * b4.y;
                acc[3][2] += a4.w * b4.z; acc[3][3] += a4.w * b4.w;
            }
            __syncthreads();
        }
#pragma unroll
        for (int i = 0; i < 4; i++) {
            int m = m0 + ty * 4 + i;
#pragma unroll
            for (int j = 0; j < 4; j++) {
                g_E[m * HH + n0 + tx * 4 + j] = acc[i][j];
            }
        }
        return;
    }
    {
        int id = bid - 1728;
        int gw = id * 8 + (tid >> 5);
        int lane = tid & 31;
        for (int r = gw; r < BB * SS; r += 1024) {
            const float4* e4 = (const float4*)(enc + r * HH);
            const float4* b4 = (const float4*)batt;
            float s = 0.f;
#pragma unroll
            for (int c = 0; c < 6; c++) {
                float4 ev = e4[c * 32 + lane];
                float4 bv = b4[c * 32 + lane];
                s += ev.x * bv.x + ev.y * bv.y + ev.z * bv.z + ev.w * bv.w;
            }
#pragma unroll
            for (int o = 16; o > 0; o >>= 1)
                s += __shfl_down_sync(0xffffffffu, s, o);
            if (lane == 0) g_e0[r] = s;
        }
    }
}

// ---------------- GRU step: 256 blocks x 384 thr, j-tile 3 -------------------
#define GRU_SMEM ((9 * 768 + 3 * 12 * 32) * 4)
__global__ void __launch_bounds__(384)
k_gru2(const float* __restrict__ Whh, const float* __restrict__ bhh, int t) {
    extern __shared__ float sm[];
    float* w_s = sm;
    float* red = w_s + 9 * 768;
    int tid = threadIdx.x;
    int j0 = blockIdx.x * 3;

    for (int i = tid; i < 1728; i += 384) {
        int row = i / 192, c4 = i % 192;
        int g = row / 3, jl = row % 3;
        *(float4*)(w_s + row * 768 + c4 * 4) =
            *(const float4*)(Whh + (g * HH + j0 + jl) * HH + c4 * 4);
    }
    __syncthreads();

    int b = tid & 31, q = tid >> 5;
    int jl = q % 3, qt = q / 3;
    int kbeg = qt * 192;
    const float4* w0 = (const float4*)(w_s + (0 + jl) * 768 + kbeg);
    const float4* w1 = (const float4*)(w_s + (3 + jl) * 768 + kbeg);
    const float4* w2 = (const float4*)(w_s + (6 + jl) * 768 + kbeg);
    const float* hp = g_hT + kbeg * 32 + b;
    float a0 = 0.f, a1 = 0.f, a2 = 0.f;
#pragma unroll 8
    for (int c = 0; c < 48; c++) {
        float4 v0 = w0[c], v1 = w1[c], v2 = w2[c];
        float h0 = hp[c * 128 + 0], h1 = hp[c * 128 + 32];
        float h2 = hp[c * 128 + 64], h3 = hp[c * 128 + 96];
        a0 += h0 * v0.x + h1 * v0.y + h2 * v0.z + h3 * v0.w;
        a1 += h0 * v1.x + h1 * v1.y + h2 * v1.z + h3 * v1.w;
        a2 += h0 * v2.x + h1 * v2.y + h2 * v2.z + h3 * v2.w;
    }
    red[(0 * 12 + q) * 32 + b] = a0;
    red[(1 * 12 + q) * 32 + b] = a1;
    red[(2 * 12 + q) * 32 + b] = a2;
    __syncthreads();

    if (tid < 96) {
        int b2 = tid & 31, j2 = tid >> 5, j = j0 + j2;
        float ar = 0.f, az = 0.f, an = 0.f;
#pragma unroll
        for (int qq = 0; qq < 4; qq++) {
            int q2 = qq * 3 + j2;
            ar += red[(0 * 12 + q2) * 32 + b2];
            az += red[(1 * 12 + q2) * 32 + b2];
            an += red[(2 * 12 + q2) * 32 + b2];
        }
        const float* gi = g_GI + (t * BB + b2) * H3;
        float r = 1.f / (1.f + expf(-(gi[j] + ar + bhh[j])));
        float z = 1.f / (1.f + expf(-(gi[HH + j] + az + bhh[HH + j])));
        float n = tanhf(gi[2 * HH + j] + r * (an + bhh[2 * HH + j]));
        float hprev = g_hT[j * 32 + b2];
        float hnew = (1.f - z) * n + z * hprev;
        g_Hbuf[(t * BB + b2) * HH + j] = hnew;
        g_hgT[j * 32 + b2] = hnew;
    }
}

// ---------------- fused attention: scores + softmax + ctx (cluster of 4) -----
// grid 128 = 32 batches x 4 ranks; rank r computes scores [32r,32r+32) into
// local smem, cluster barrier, gathers all 128 via DSMEM, local softmax,
// then writes its 192-dim ctx chunk to g_ctxT.
__global__ void __cluster_dims__(4, 1, 1) __launch_bounds__(256)
k_attn(const float* __restrict__ enc, int t) {
    __shared__ __align__(16) float hg[768];
    __shared__ float scl[32];
    __shared__ float p[128];
    __shared__ float red[128];
    int tid = threadIdx.x;
    int b = blockIdx.x >> 2;
    u32 rank;
    asm("mov.u32 %0, %%cluster_ctarank;" : "=r"(rank));

    for (int i = tid; i < 768; i += 256) hg[i] = g_Hbuf[(t * BB + b) * HH + i];
    __syncthreads();

    int w = tid >> 5, lane = tid & 31;
    const float4* hg4 = (const float4*)hg;
#pragma unroll
    for (int i = 0; i < 4; i++) {
        int sl = w * 4 + i;                   // 0..31 local score idx
        int s = (int)rank * 32 + sl;
        const float4* e4 = (const float4*)(g_E + (b * SS + s) * HH);
        float d = 0.f;
#pragma unroll
        for (int c = 0; c < 6; c++) {
            float4 ev = e4[c * 32 + lane];
            float4 hv = hg4[c * 32 + lane];
            d += ev.x * hv.x + ev.y * hv.y + ev.z * hv.z + ev.w * hv.w;
        }
#pragma unroll
        for (int o = 16; o > 0; o >>= 1) d += __shfl_down_sync(0xffffffffu, d, o);
        if (lane == 0) scl[sl] = d + g_e0[b * SS + s];
    }

    // all ranks' scores visible after cluster barrier (release/acquire)
    cluster_sync_aligned();

    if (tid < 128) {
        u32 laddr = smem_addr_u32(&scl[tid & 31]);
        float v = dsmem_ld_f32(laddr, (u32)(tid >> 5));
        p[tid] = v;
        red[tid] = v;
    }
    __syncthreads();
    for (int o = 64; o > 0; o >>= 1) {
        if (tid < o) red[tid] = fmaxf(red[tid], red[tid + o]);
        __syncthreads();
    }
    float mx = red[0];
    __syncthreads();
    if (tid < 128) {
        float e = expf(p[tid] - mx);
        p[tid] = e;
        red[tid] = e;
    }
    __syncthreads();
    for (int o = 64; o > 0; o >>= 1) {
        if (tid < o) red[tid] += red[tid + o];
        __syncthreads();
    }
    float inv = 1.f / red[0];
    __syncthreads();
    if (tid < 128) p[tid] *= inv;
    __syncthreads();

    if (tid < 192) {
        int dim = (int)rank * 192 + tid;
        float acc = 0.f;
        const float* ep = enc + (b * SS) * HH + dim;
#pragma unroll 8
        for (int s = 0; s < SS; s++) acc += p[s] * ep[s * HH];
        g_ctxT[dim * 32 + b] = acc;
    }

    // no CTA may exit while peers might still read its scl via DSMEM
    cluster_sync_aligned();
}

// ---------------- carry update: 256 blocks x 384 thr, j-tile 3 ---------------
#define ATTH_SMEM ((3 * 1536 + 12 * 32) * 4)
__global__ void __launch_bounds__(384)
k_atth2(const float* __restrict__ Wctx, const float* __restrict__ bctx,
        int t) {
    extern __shared__ float sm[];
    float* w_s = sm;
    float* red = w_s + 3 * 1536;
    int tid = threadIdx.x;
    int j0 = blockIdx.x * 3;

    for (int i = tid; i < 1152; i += 384) {
        int row = i / 384, c4 = i % 384;
        *(float4*)(w_s + row * 1536 + c4 * 4) =
            *(const float4*)(Wctx + (j0 + row) * (2 * HH) + c4 * 4);
    }
    __syncthreads();

    int b = tid & 31, q = tid >> 5;
    int jl = q % 3, sub = q / 3;
    float acc = 0.f;
#pragma unroll
    for (int ph = 0; ph < 2; ph++) {
        const float* ip = (ph ? g_hgT : g_ctxT) + sub * 192 * 32 + b;
        const float4* wp =
            (const float4*)(w_s + jl * 1536 + ph * 768 + sub * 192);
#pragma unroll 8
        for (int c = 0; c < 48; c++) {
            float4 v = wp[c];
            float h0 = ip[c * 128 + 0], h1 = ip[c * 128 + 32];
            float h2 = ip[c * 128 + 64], h3 = ip[c * 128 + 96];
            acc += h0 * v.x + h1 * v.y + h2 * v.z + h3 * v.w;
        }
    }
    red[q * 32 + b] = acc;
    __syncthreads();
    if (tid < 96) {
        int b2 = tid & 31, j2 = tid >> 5, j = j0 + j2;
        float s = 0.f;
#pragma unroll
        for (int qq = 0; qq < 4; qq++) s += red[(qq * 3 + j2) * 32 + b2];
        g_hT[j * 32 + b2] = tanhf(s + bctx[j]);
    }
}

// ---------------- bf16 split conversions ------------------------------------
__device__ __forceinline__ void split4(float4 v, __nv_bfloat16* hi,
                                       __nv_bfloat16* lo) {
    float f[4];
    f[0] = v.x; f[1] = v.y; f[2] = v.z; f[3] = v.w;
#pragma unroll
    for (int i = 0; i < 4; i++) {
        __nv_bfloat16 h = __float2bfloat16_rn(f[i]);
        hi[i] = h;
        lo[i] = __float2bfloat16_rn(f[i] - __bfloat162float(h));
    }
}

// B' = [Bh | Bl | Bh], rows padded to VPAD with zeros
__global__ void k_cvtB(const float* __restrict__ Wp) {
    long idx = (long)blockIdx.x * blockDim.x + threadIdx.x;
    if (idx >= (long)VPAD * 192) return;
    int row = (int)(idx / 192), c4 = (int)(idx % 192);
    float4 v = (row < VV) ? *(const float4*)(Wp + (long)row * HH + c4 * 4)
                          : make_float4(0.f, 0.f, 0.f, 0.f);
    __nv_bfloat16 hi[4], lo[4];
    split4(v, hi, lo);
    __nv_bfloat16* dst = g_Bs + (long)row * KS + c4 * 4;
    *(uint2*)(dst) = *(uint2*)hi;
    *(uint2*)(dst + HH) = *(uint2*)lo;
    *(uint2*)(dst + 2 * HH) = *(uint2*)hi;
}

// A' = [Ah | Ah | Al]
__global__ void k_cvtA() {
    int idx = blockIdx.x * blockDim.x + threadIdx.x;
    if (idx >= TT * BB * 192) return;
    int row = idx / 192, c4 = idx % 192;
    float4 v = *(const float4*)(g_Hbuf + row * HH + c4 * 4);
    __nv_bfloat16 hi[4], lo[4];
    split4(v, hi, lo);
    __nv_bfloat16* dst = g_As + row * KS + c4 * 4;
    *(uint2*)(dst) = *(uint2*)hi;
    *(uint2*)(dst + HH) = *(uint2*)hi;
    *(uint2*)(dst + 2 * HH) = *(uint2*)lo;
}

// ---------------- logits GEMM on tensor cores (mma.sync bf16) ----------------
// K slab 64 (NIT=36). Rows padded to 72 bf16 (144 B).
#define LDP2 72
#define PSTG (128 * LDP2)
#define PRED_SMEM (4 * PSTG * 2)          // 73728 B dynamic smem
__global__ void __launch_bounds__(256)
k_predmma(const float* __restrict__ bp, float* __restrict__ out) {
    extern __shared__ __nv_bfloat16 smp[];
    __nv_bfloat16* sA = smp;
    __nv_bfloat16* sB = smp + 2 * PSTG;

    int tid = threadIdx.x;
    int lane = tid & 31, wid = tid >> 5;
    int m0 = blockIdx.x * 128, n0 = blockIdx.y * 128;
    int warp_m = (wid >> 1) * 32;
    int warp_n = (wid & 1) * 64;

    const __nv_bfloat16* gA = g_As + (long)m0 * KS;
    const __nv_bfloat16* gB = g_Bs + (long)n0 * KS;

    float acc[2][8][4];
#pragma unroll
    for (int i = 0; i < 2; i++)
#pragma unroll
        for (int j = 0; j < 8; j++)
#pragma unroll
            for (int r = 0; r < 4; r++) acc[i][j][r] = 0.f;

    int cr[4], cc[4];
#pragma unroll
    for (int j = 0; j < 4; j++) {
        int c = tid + j * 256;
        cr[j] = c >> 3;
        cc[j] = (c & 7) * 8;
    }

    u32 sA0 = (u32)__cvta_generic_to_shared(sA);
    u32 sB0 = (u32)__cvta_generic_to_shared(sB);
    const u32 stage = PSTG * 2;

#pragma unroll
    for (int j = 0; j < 4; j++) {
        cp_async16(sA0 + (cr[j] * LDP2 + cc[j]) * 2, gA + (long)cr[j] * KS + cc[j]);
        cp_async16(sB0 + (cr[j] * LDP2 + cc[j]) * 2, gB + (long)cr[j] * KS + cc[j]);
    }
    cp_commit();

    const int NIT = KS / 64;  // 36
    for (int it = 0; it < NIT; it++) {
        int buf = it & 1;
        if (it + 1 < NIT) {
            int k0 = (it + 1) * 64;
            u32 dA = sA0 + (buf ^ 1) * stage;
            u32 dB = sB0 + (buf ^ 1) * stage;
#pragma unroll
            for (int j = 0; j < 4; j++) {
                cp_async16(dA + (cr[j] * LDP2 + cc[j]) * 2,
                           gA + (long)cr[j] * KS + k0 + cc[j]);
                cp_async16(dB + (cr[j] * LDP2 + cc[j]) * 2,
                           gB + (long)cr[j] * KS + k0 + cc[j]);
            }
            cp_commit();
            cp_wait<1>();
        } else {
            cp_wait<0>();
        }
        __syncthreads();

        u32 baseA = sA0 + buf * stage;
        u32 baseB = sB0 + buf * stage;
#pragma unroll
        for (int ks = 0; ks < 4; ks++) {
            u32 areg[2][4];
#pragma unroll
            for (int mi = 0; mi < 2; mi++) {
                u32 addr = baseA +
                    ((warp_m + mi * 16 + (lane & 15)) * LDP2 +
                     ks * 16 + (lane >> 4) * 8) * 2;
                ldsm_x4(areg[mi][0], areg[mi][1], areg[mi][2], areg[mi][3],
                        addr);
            }
            u32 breg[4][4];
#pragma unroll
            for (int np = 0; np < 4; np++) {
                u32 addr = baseB +
                    ((warp_n + np * 16 + (lane & 15)) * LDP2 +
                     ks * 16 + (lane >> 4) * 8) * 2;
                ldsm_x4(breg[np][0], breg[np][1], breg[np][2], breg[np][3],
                        addr);
            }
#pragma unroll
            for (int mi = 0; mi < 2; mi++) {
#pragma unroll
                for (int nf = 0; nf < 8; nf++) {
                    int np = nf >> 1;
                    u32 b0 = (nf & 1) ? breg[np][1] : breg[np][0];
                    u32 b1 = (nf & 1) ? breg[np][3] : breg[np][2];
                    mma_bf16_16816(acc[mi][nf][0], acc[mi][nf][1],
                                   acc[mi][nf][2], acc[mi][nf][3],
                                   areg[mi][0], areg[mi][1], areg[mi][2],
                                   areg[mi][3], b0, b1);
                }
            }
        }
        __syncthreads();
    }

#pragma unroll
    for (int mi = 0; mi < 2; mi++) {
        int mA = m0 + warp_m + mi * 16 + (lane >> 2);
#pragma unroll
        for (int half = 0; half < 2; half++) {
            int m = mA + half * 8;
            int t = m >> 5, bb = m & 31;
            float* orow = out + (long)(bb * TT + t) * VV;
#pragma unroll
            for (int nf = 0; nf < 8; nf++) {
                int n = n0 + warp_n + nf * 8 + (lane & 3) * 2;
                if (n < VV) {
                    float2 bias = *(const float2*)(bp + n);
                    float2 v;
                    v.x = acc[mi][nf][half * 2 + 0] + bias.x;
                    v.y = acc[mi][nf][half * 2 + 1] + bias.y;
                    *(float2*)(orow + n) = v;
                }
            }
        }
    }
}

// ---------------- launcher ---------------------------------------------------
extern "C" void kernel_launch(void* const* d_in, const int* in_sizes, int n_in,
                              void* d_out, int out_size) {
    const float* x    = (const float*)d_in[0];
    const float* h0   = (const float*)d_in[1];
    const float* enc  = (const float*)d_in[2];
    const float* Wih  = (const float*)d_in[3];
    const float* Whh  = (const float*)d_in[4];
    const float* bih  = (const float*)d_in[5];
    const float* bhh  = (const float*)d_in[6];
    const float* Wp   = (const float*)d_in[7];
    const float* bp   = (const float*)d_in[8];
    const float* Watt = (const float*)d_in[9];
    const float* batt = (const float*)d_in[10];
    const float* Wctx = (const float*)d_in[11];
    const float* bctx = (const float*)d_in[12];
    float* out = (float*)d_out;

    cudaFuncSetAttribute(k_gru2, cudaFuncAttributeMaxDynamicSharedMemorySize,
                         GRU_SMEM);
    cudaFuncSetAttribute(k_atth2, cudaFuncAttributeMaxDynamicSharedMemorySize,
                         ATTH_SMEM);
    cudaFuncSetAttribute(k_predmma, cudaFuncAttributeMaxDynamicSharedMemorySize,
                         PRED_SMEM);

    k_prolog<<<PROLOG_BLOCKS, 256>>>(x, Wih, bih, enc, Watt, batt, h0);
    k_cvtB<<<(VPAD * 192 + 255) / 256, 256>>>(Wp);

    for (int t = 0; t < TT; t++) {
        k_gru2<<<256, 384, GRU_SMEM>>>(Whh, bhh, t);
        k_attn<<<BB * 4, 256>>>(enc, t);
        k_atth2<<<256, 384, ATTH_SMEM>>>(Wctx, bctx, t);
    }

    k_cvtA<<<(TT * BB * 192 + 255) / 256, 256>>>();
    k_predmma<<<dim3((TT * BB) / 128, VPAD / 128), 256, PRED_SMEM>>>(bp, out);
}